// round 1
// baseline (speedup 1.0000x reference)
#include <cuda_runtime.h>
#include <math.h>

#define N_NODES 51200
#define N_EDGES 819200
#define NG 512
#define NPG 100
#define EPG 1600
#define HID 512
#define FIN 128
#define EPSV 1e-5f

#define OUT_LOGP 0
#define OUT_POS 3072
#define OUT_GEMB 265216
#define OUT_PEN 527360

// ---------------- scratch (static device allocations; no cudaMalloc) --------
__device__ float d_deg[N_NODES];
__device__ float d_dis[N_NODES];
__device__ float d_A[NG * NPG * NPG];       // dense normalized adjacency per graph
__device__ float d_T[N_NODES * HID];        // GEMM output / U / Z scratch
__device__ float d_Hb[N_NODES * HID];       // h buffer
__device__ float d_assign[N_NODES * 2];
__device__ float d_pos[NG * HID];
__device__ float d_gvec[HID];
__device__ float d_newadj[NG * 4];
__device__ float d_scal[4];

// ---------------- setup kernels --------------------------------------------
__global__ void k_zero_misc() {
    int i = blockIdx.x * blockDim.x + threadIdx.x;
    if (i < N_NODES) d_deg[i] = 0.f;
    if (i < HID) d_gvec[i] = 0.f;
    if (i < 4) d_scal[i] = 0.f;
}

__global__ void k_zeroA() {
    int i = blockIdx.x * blockDim.x + threadIdx.x;
    if (i < NG * NPG * NPG) d_A[i] = 0.f;
}

__global__ void k_deg(const int* __restrict__ ei) {
    int e = blockIdx.x * blockDim.x + threadIdx.x;
    if (e < N_EDGES) atomicAdd(&d_deg[ei[N_EDGES + e]], 1.0f);
}

__global__ void k_dis() {
    int i = blockIdx.x * blockDim.x + threadIdx.x;
    if (i < N_NODES) d_dis[i] = rsqrtf(d_deg[i] + 1.0f);
}

__global__ void k_diag() {  // self-loop term dis^2 on diagonal (A freshly zeroed)
    int i = blockIdx.x * blockDim.x + threadIdx.x;
    if (i < N_NODES) {
        int g = i / NPG, l = i % NPG;
        d_A[g * NPG * NPG + l * NPG + l] = d_dis[i] * d_dis[i];
    }
}

__global__ void k_edgeA(const int* __restrict__ ei) {
    int e = blockIdx.x * blockDim.x + threadIdx.x;
    if (e < N_EDGES) {
        int s = ei[e];
        int d = ei[N_EDGES + e];
        float w = d_dis[s] * d_dis[d];
        int g = d / NPG;
        atomicAdd(&d_A[g * NPG * NPG + (d % NPG) * NPG + (s % NPG)], w);
    }
}

// ---------------- tiled SGEMM: C[M,N] = A[M,K] @ B[K,N] (+bias, +act) ------
// EPI: 0 = none, 1 = bias+tanh, 2 = bias+relu
template <int EPI>
__global__ void sgemm(const float* __restrict__ A, const float* __restrict__ B,
                      const float* __restrict__ bias, float* __restrict__ C,
                      int M, int N, int K) {
    __shared__ float As[8][128];
    __shared__ float Bs[8][128];
    int tid = threadIdx.x;          // 256 threads
    int m0 = blockIdx.y * 128;
    int n0 = blockIdx.x * 128;
    int arow = tid >> 1;
    int acol = (tid & 1) * 4;
    int brow = tid >> 5;
    int bcol = (tid & 31) * 4;
    int ty = tid >> 4;              // 0..15
    int tx = tid & 15;              // 0..15
    float acc[8][8] = {};

    for (int k0 = 0; k0 < K; k0 += 8) {
        float4 av = *(const float4*)(A + (size_t)(m0 + arow) * K + k0 + acol);
        As[acol + 0][arow] = av.x;
        As[acol + 1][arow] = av.y;
        As[acol + 2][arow] = av.z;
        As[acol + 3][arow] = av.w;
        *(float4*)(&Bs[brow][bcol]) =
            *(const float4*)(B + (size_t)(k0 + brow) * N + n0 + bcol);
        __syncthreads();
#pragma unroll
        for (int k = 0; k < 8; ++k) {
            float a[8], b[8];
            *(float4*)(a) = *(float4*)(&As[k][ty * 8]);
            *(float4*)(a + 4) = *(float4*)(&As[k][ty * 8 + 4]);
            *(float4*)(b) = *(float4*)(&Bs[k][tx * 8]);
            *(float4*)(b + 4) = *(float4*)(&Bs[k][tx * 8 + 4]);
#pragma unroll
            for (int i = 0; i < 8; ++i)
#pragma unroll
                for (int j = 0; j < 8; ++j) acc[i][j] = fmaf(a[i], b[j], acc[i][j]);
        }
        __syncthreads();
    }
#pragma unroll
    for (int i = 0; i < 8; ++i) {
        int row = m0 + ty * 8 + i;
#pragma unroll
        for (int j = 0; j < 8; j += 4) {
            int col = n0 + tx * 8 + j;
            float4 v = make_float4(acc[i][j], acc[i][j + 1], acc[i][j + 2], acc[i][j + 3]);
            if (EPI != 0) {
                float4 bb = *(const float4*)(bias + col);
                v.x += bb.x; v.y += bb.y; v.z += bb.z; v.w += bb.w;
                if (EPI == 1) {
                    v.x = tanhf(v.x); v.y = tanhf(v.y); v.z = tanhf(v.z); v.w = tanhf(v.w);
                } else {
                    v.x = fmaxf(v.x, 0.f); v.y = fmaxf(v.y, 0.f);
                    v.z = fmaxf(v.z, 0.f); v.w = fmaxf(v.w, 0.f);
                }
            }
            *(float4*)(C + (size_t)row * N + col) = v;
        }
    }
}

// ---------------- per-graph dense aggregation: H = A_g @ T_g + b ------------
// block: (graph g, row-half rh). 128 threads, each owns 4 output cols.
// smem: A half-rows [50][100] (20 KB) + full T tile [100][512] (204.8 KB)
#define AGG_SMEM ((50 * 100 + 100 * 512) * 4)
__global__ void k_agg(const float* __restrict__ T, const float* __restrict__ bias,
                      float* __restrict__ Hout) {
    extern __shared__ float sh[];
    float* Ash = sh;            // 50*100
    float* Tsh = sh + 5000;     // 100*512
    int g = blockIdx.x, rh = blockIdx.y;
    int tid = threadIdx.x;      // 128

    const float* Ag = d_A + g * NPG * NPG + rh * 50 * NPG;
    for (int i = tid; i < 5000; i += 128) Ash[i] = Ag[i];
    const float4* Tg = (const float4*)(T + (size_t)g * NPG * HID);
    float4* T4 = (float4*)Tsh;
    for (int i = tid; i < NPG * 128; i += 128) T4[i] = Tg[i];
    __syncthreads();

    int c = tid * 4;
    float4 bv = *(const float4*)(bias + c);
#pragma unroll 1
    for (int r0 = 0; r0 < 50; r0 += 10) {
        float4 acc[10];
#pragma unroll
        for (int i = 0; i < 10; ++i) acc[i] = make_float4(0.f, 0.f, 0.f, 0.f);
        for (int k = 0; k < NPG; ++k) {
            float4 t = *(float4*)(Tsh + k * HID + c);
#pragma unroll
            for (int i = 0; i < 10; ++i) {
                float a = Ash[(r0 + i) * NPG + k];
                acc[i].x = fmaf(a, t.x, acc[i].x);
                acc[i].y = fmaf(a, t.y, acc[i].y);
                acc[i].z = fmaf(a, t.z, acc[i].z);
                acc[i].w = fmaf(a, t.w, acc[i].w);
            }
        }
#pragma unroll
        for (int i = 0; i < 10; ++i) {
            int row = g * NPG + rh * 50 + r0 + i;
            float4 v = make_float4(acc[i].x + bv.x, acc[i].y + bv.y,
                                   acc[i].z + bv.z, acc[i].w + bv.w);
            *(float4*)(Hout + (size_t)row * HID + c) = v;
        }
    }
}

// ---------------- assignment: softmax(U @ Wc2 + bc2), warp per node --------
__global__ void k_assign(const float* __restrict__ U, const float* __restrict__ Wc2,
                         const float* __restrict__ bc2) {
    __shared__ float w[HID * 2];
    int tid = threadIdx.x;
    for (int i = tid; i < HID * 2; i += 128) w[i] = Wc2[i];
    __syncthreads();
    int warp = tid >> 5, lane = tid & 31;
    int n = blockIdx.x * 4 + warp;
    const float* u = U + (size_t)n * HID;
    float s0 = 0.f, s1 = 0.f;
    for (int k = lane; k < HID; k += 32) {
        float uv = u[k];
        s0 = fmaf(uv, w[2 * k], s0);
        s1 = fmaf(uv, w[2 * k + 1], s1);
    }
#pragma unroll
    for (int o = 16; o > 0; o >>= 1) {
        s0 += __shfl_xor_sync(0xffffffff, s0, o);
        s1 += __shfl_xor_sync(0xffffffff, s1, o);
    }
    if (lane == 0) {
        float z0 = s0 + bc2[0], z1 = s1 + bc2[1];
        float m = fmaxf(z0, z1);
        float e0 = expf(z0 - m), e1 = expf(z1 - m);
        float inv = 1.f / (e0 + e1);
        d_assign[n * 2] = e0 * inv;
        d_assign[n * 2 + 1] = e1 * inv;
    }
}

// ---------------- pos (S^T x row 0) + global h column sums -----------------
__global__ void k_pos() {
    __shared__ float a0[NPG];
    int g = blockIdx.x, c = threadIdx.x;  // 512 threads
    if (c < NPG) a0[c] = d_assign[(g * NPG + c) * 2];
    __syncthreads();
    const float* h = d_Hb + (size_t)g * NPG * HID;
    float acc = 0.f, gs = 0.f;
    for (int n = 0; n < NPG; ++n) {
        float hv = h[n * HID + c];
        acc = fmaf(a0[n], hv, acc);
        gs += hv;
    }
    d_pos[g * HID + c] = acc;
    atomicAdd(&d_gvec[c], gs);
}

// ---------------- new_adj = sum over edges of outer(s_src, s_dst) ----------
__global__ void k_newadj(const int* __restrict__ ei) {
    __shared__ float sa[NPG * 2];
    __shared__ float red[4][4];
    int g = blockIdx.x, tid = threadIdx.x;  // 128 threads
    if (tid < NPG * 2) sa[tid] = d_assign[g * NPG * 2 + tid];
    __syncthreads();
    float a00 = 0, a01 = 0, a10 = 0, a11 = 0;
    for (int e = tid; e < EPG; e += 128) {
        int s = ei[g * EPG + e] - g * NPG;
        int d = ei[N_EDGES + g * EPG + e] - g * NPG;
        float s0 = sa[2 * s], s1 = sa[2 * s + 1];
        float t0 = sa[2 * d], t1 = sa[2 * d + 1];
        a00 = fmaf(s0, t0, a00); a01 = fmaf(s0, t1, a01);
        a10 = fmaf(s1, t0, a10); a11 = fmaf(s1, t1, a11);
    }
#pragma unroll
    for (int o = 16; o > 0; o >>= 1) {
        a00 += __shfl_xor_sync(0xffffffff, a00, o);
        a01 += __shfl_xor_sync(0xffffffff, a01, o);
        a10 += __shfl_xor_sync(0xffffffff, a10, o);
        a11 += __shfl_xor_sync(0xffffffff, a11, o);
    }
    int warp = tid >> 5, lane = tid & 31;
    if (lane == 0) {
        red[warp][0] = a00; red[warp][1] = a01;
        red[warp][2] = a10; red[warp][3] = a11;
    }
    __syncthreads();
    if (tid < 4) {
        float v = red[0][tid] + red[1][tid] + red[2][tid] + red[3][tid];
        d_newadj[g * 4 + tid] = v;
    }
}

__global__ void k_penalty(float* __restrict__ out) {
    __shared__ float red[NG];
    int g = threadIdx.x;  // 512
    float a00 = d_newadj[g * 4], a01 = d_newadj[g * 4 + 1];
    float a10 = d_newadj[g * 4 + 2], a11 = d_newadj[g * 4 + 3];
    float r0 = fmaxf(fabsf(a00) + fabsf(a01), EPSV);
    float r1 = fmaxf(fabsf(a10) + fabsf(a11), EPSV);
    float dd0 = a00 / r0 - 1.f, dd1 = a11 / r1 - 1.f;
    red[g] = dd0 * dd0 + dd1 * dd1;
    __syncthreads();
    for (int s = 256; s > 0; s >>= 1) {
        if (g < s) red[g] += red[g + s];
        __syncthreads();
    }
    if (g == 0) out[OUT_PEN] = red[0] * (1.f / (NG * 2.f));
}

// ---------------- norm reductions ------------------------------------------
__global__ void k_sumsq_pos() {
    __shared__ float red[256];
    int tid = threadIdx.x;
    float s = 0.f;
    for (int i = blockIdx.x * 256 + tid; i < NG * HID; i += gridDim.x * 256) {
        float v = d_pos[i];
        s = fmaf(v, v, s);
    }
    red[tid] = s;
    __syncthreads();
    for (int o = 128; o > 0; o >>= 1) {
        if (tid < o) red[tid] += red[tid + o];
        __syncthreads();
    }
    if (tid == 0) atomicAdd(&d_scal[0], red[0]);
}

__global__ void k_pg() {
    __shared__ float red[HID];
    int t = threadIdx.x;  // 512
    float v = d_gvec[t] * (1.f / (float)N_NODES);
    red[t] = v * v;
    __syncthreads();
    for (int s = 256; s > 0; s >>= 1) {
        if (t < s) red[t] += red[t + s];
        __syncthreads();
    }
    if (t == 0) d_scal[1] = red[0] * (1.f / (float)HID);
}

__global__ void k_finpos(float* __restrict__ out) {
    int i = blockIdx.x * blockDim.x + threadIdx.x;
    if (i < NG * HID) {
        float ms = d_scal[0] * (1.f / (float)(NG * HID));
        float sc = (ms > 1.f) ? rsqrtf(ms) : 1.f;
        float v = d_pos[i] * sc;
        d_pos[i] = v;
        out[OUT_POS + i] = v;
    }
}

__global__ void k_fingemb(float* __restrict__ out) {
    int i = blockIdx.x * blockDim.x + threadIdx.x;
    if (i < NG * HID) {
        float ms = d_scal[1];
        float sc = (ms > 1.f) ? rsqrtf(ms) : 1.f;
        float v = d_gvec[i & (HID - 1)] * (1.f / (float)N_NODES) * sc;
        out[OUT_GEMB + i] = v;
    }
}

// ---------------- head: o = Z @ Wl2 + bl2; log_softmax ---------------------
__global__ void k_head(const float* __restrict__ Z, const float* __restrict__ Wl2,
                       const float* __restrict__ bl2, float* __restrict__ out) {
    __shared__ float w[HID * 6];
    int tid = threadIdx.x;  // 128
    for (int i = tid; i < HID * 6; i += 128) w[i] = Wl2[i];
    __syncthreads();
    int warp = tid >> 5, lane = tid & 31;
    int row = blockIdx.x * 4 + warp;
    const float* z = Z + (size_t)row * HID;
    float s[6] = {0, 0, 0, 0, 0, 0};
    for (int k = lane; k < HID; k += 32) {
        float zv = z[k];
#pragma unroll
        for (int j = 0; j < 6; ++j) s[j] = fmaf(zv, w[k * 6 + j], s[j]);
    }
#pragma unroll
    for (int o = 16; o > 0; o >>= 1)
#pragma unroll
        for (int j = 0; j < 6; ++j) s[j] += __shfl_xor_sync(0xffffffff, s[j], o);
    if (lane == 0) {
        float o6[6], m = -1e30f;
#pragma unroll
        for (int j = 0; j < 6; ++j) { o6[j] = s[j] + bl2[j]; m = fmaxf(m, o6[j]); }
        float sum = 0.f;
#pragma unroll
        for (int j = 0; j < 6; ++j) sum += expf(o6[j] - m);
        float lse = m + logf(sum);
#pragma unroll
        for (int j = 0; j < 6; ++j) out[OUT_LOGP + row * 6 + j] = o6[j] - lse;
    }
}

// ---------------- launch ----------------------------------------------------
extern "C" void kernel_launch(void* const* d_in, const int* in_sizes, int n_in,
                              void* d_out, int out_size) {
    const float* x   = (const float*)d_in[0];
    const int*   ei  = (const int*)d_in[1];
    const float* W1  = (const float*)d_in[4];
    const float* b1  = (const float*)d_in[5];
    const float* W2  = (const float*)d_in[6];
    const float* b2  = (const float*)d_in[7];
    const float* W3  = (const float*)d_in[8];
    const float* b3  = (const float*)d_in[9];
    const float* Wc1 = (const float*)d_in[10];
    const float* bc1 = (const float*)d_in[11];
    const float* Wc2 = (const float*)d_in[12];
    const float* bc2 = (const float*)d_in[13];
    const float* Wl1 = (const float*)d_in[14];
    const float* bl1 = (const float*)d_in[15];
    const float* Wl2 = (const float*)d_in[16];
    const float* bl2 = (const float*)d_in[17];
    float* out = (float*)d_out;

    float *pT, *pH, *pPos;
    cudaGetSymbolAddress((void**)&pT, d_T);
    cudaGetSymbolAddress((void**)&pH, d_Hb);
    cudaGetSymbolAddress((void**)&pPos, d_pos);

    cudaFuncSetAttribute(k_agg, cudaFuncAttributeMaxDynamicSharedMemorySize, AGG_SMEM);

    // graph structure
    k_zero_misc<<<200, 256>>>();
    k_zeroA<<<20000, 256>>>();
    k_deg<<<3200, 256>>>(ei);
    k_dis<<<200, 256>>>();
    k_diag<<<200, 256>>>();
    k_edgeA<<<3200, 256>>>(ei);

    dim3 gBig(HID / 128, N_NODES / 128);
    dim3 gAgg(NG, 2);

    // 3 GCN layers: T = H@W ; H = A_hat @ T + b
    sgemm<0><<<gBig, 256>>>(x, W1, nullptr, pT, N_NODES, HID, FIN);
    k_agg<<<gAgg, 128, AGG_SMEM>>>(pT, b1, pH);
    sgemm<0><<<gBig, 256>>>(pH, W2, nullptr, pT, N_NODES, HID, HID);
    k_agg<<<gAgg, 128, AGG_SMEM>>>(pT, b2, pH);
    sgemm<0><<<gBig, 256>>>(pH, W3, nullptr, pT, N_NODES, HID, HID);
    k_agg<<<gAgg, 128, AGG_SMEM>>>(pT, b3, pH);

    // assignment = softmax(tanh(h@Wc1+bc1)@Wc2+bc2)
    sgemm<1><<<gBig, 256>>>(pH, Wc1, bc1, pT, N_NODES, HID, HID);
    k_assign<<<N_NODES / 4, 128>>>(pT, Wc2, bc2);

    // pooling / penalty
    k_pos<<<NG, HID>>>();
    k_newadj<<<NG, 128>>>(ei);
    k_penalty<<<1, NG>>>(out);

    // normalizations
    k_sumsq_pos<<<256, 256>>>();
    k_pg<<<1, HID>>>();
    k_finpos<<<1024, 256>>>(out);
    k_fingemb<<<1024, 256>>>(out);

    // head MLP on normalized pos
    dim3 gHead(HID / 128, NG / 128);
    sgemm<2><<<gHead, 256>>>(pPos, Wl1, bl1, pT, NG, HID, HID);
    k_head<<<NG / 4, 128>>>(pT, Wl2, bl2, out);
}

// round 4
// speedup vs baseline: 1.7039x; 1.7039x over previous
#include <cuda_runtime.h>
#include <math.h>
#include <cstdint>

#define N_NODES 51200
#define N_EDGES 819200
#define NG 512
#define NPG 100
#define EPG 1600
#define HID 512
#define FIN 128
#define EPSV 1e-5f

#define OUT_LOGP 0
#define OUT_POS 3072
#define OUT_GEMB 265216
#define OUT_PEN 527360

// ---------------- scratch (static device allocations; no cudaMalloc) --------
__device__ float d_deg[N_NODES];
__device__ float d_dis[N_NODES];
__device__ float d_A[NG * NPG * NPG];
__device__ float d_T[N_NODES * HID];
__device__ float d_Hb[N_NODES * HID];
__device__ float d_assign[N_NODES * 2];
__device__ float d_pos[NG * HID];
__device__ float d_gvec[HID];
__device__ float d_newadj[NG * 4];
__device__ float d_scal[4];
__device__ float d_Wt[4][HID * HID];   // transposed + tf32-rounded weights [N][K]

// ---------------- ptx helpers ----------------------------------------------
__device__ __forceinline__ uint32_t s2u(const void* p) {
    uint32_t a;
    asm("{ .reg .u64 t; cvta.to.shared.u64 t, %1; cvt.u32.u64 %0, t; }"
        : "=r"(a) : "l"(p));
    return a;
}
__device__ __forceinline__ float rna_tf32(float v) {
    uint32_t o;
    asm("cvt.rna.tf32.f32 %0, %1;" : "=r"(o) : "f"(v));
    return __uint_as_float(o);
}
__device__ __forceinline__ void cp16(uint32_t s, const void* g) {
    asm volatile("cp.async.cg.shared.global [%0], [%1], 16;" :: "r"(s), "l"(g));
}
__device__ __forceinline__ void mma_tf32_16n8k8(float* c, const uint32_t* a,
                                                const uint32_t* b) {
    asm volatile(
        "mma.sync.aligned.m16n8k8.row.col.f32.tf32.tf32.f32 "
        "{%0,%1,%2,%3}, {%4,%5,%6,%7}, {%8,%9}, {%0,%1,%2,%3};"
        : "+f"(c[0]), "+f"(c[1]), "+f"(c[2]), "+f"(c[3])
        : "r"(a[0]), "r"(a[1]), "r"(a[2]), "r"(a[3]), "r"(b[0]), "r"(b[1]));
}

// ---------------- setup kernels --------------------------------------------
__global__ void k_zero_misc() {
    int i = blockIdx.x * blockDim.x + threadIdx.x;
    if (i < N_NODES) d_deg[i] = 0.f;
    if (i < HID) d_gvec[i] = 0.f;
    if (i < 4) d_scal[i] = 0.f;
}
__global__ void k_zeroA() {
    int i = blockIdx.x * blockDim.x + threadIdx.x;
    if (i < NG * NPG * NPG) d_A[i] = 0.f;
}
__global__ void k_deg(const int* __restrict__ ei) {
    int e = blockIdx.x * blockDim.x + threadIdx.x;
    if (e < N_EDGES) atomicAdd(&d_deg[ei[N_EDGES + e]], 1.0f);
}
__global__ void k_dis() {
    int i = blockIdx.x * blockDim.x + threadIdx.x;
    if (i < N_NODES) d_dis[i] = rsqrtf(d_deg[i] + 1.0f);
}
__global__ void k_diag() {
    int i = blockIdx.x * blockDim.x + threadIdx.x;
    if (i < N_NODES) {
        int g = i / NPG, l = i % NPG;
        d_A[g * NPG * NPG + l * NPG + l] = d_dis[i] * d_dis[i];
    }
}
__global__ void k_edgeA(const int* __restrict__ ei) {
    int e = blockIdx.x * blockDim.x + threadIdx.x;
    if (e < N_EDGES) {
        int s = ei[e];
        int d = ei[N_EDGES + e];
        float w = d_dis[s] * d_dis[d];
        int g = d / NPG;
        atomicAdd(&d_A[g * NPG * NPG + (d % NPG) * NPG + (s % NPG)], w);
    }
}

// ---------------- weight transpose + tf32 rounding: Wt[n][k] = rna(W[k][n]) -
__global__ void k_transpose(const float* __restrict__ W, float* __restrict__ Wt,
                            int K, int N) {
    __shared__ float tile[32][33];
    int k0 = blockIdx.y * 32, n0 = blockIdx.x * 32;
    int tx = threadIdx.x, ty = threadIdx.y;  // 32 x 8
    for (int j = ty; j < 32; j += 8) tile[j][tx] = W[(size_t)(k0 + j) * N + n0 + tx];
    __syncthreads();
    for (int j = ty; j < 32; j += 8)
        Wt[(size_t)(n0 + j) * K + k0 + tx] = rna_tf32(tile[tx][j]);
}

__global__ void k_round_x(const float4* __restrict__ x, float4* __restrict__ o) {
    int i = blockIdx.x * blockDim.x + threadIdx.x;
    if (i < N_NODES * FIN / 4) {
        float4 v = x[i];
        v.x = rna_tf32(v.x); v.y = rna_tf32(v.y);
        v.z = rna_tf32(v.z); v.w = rna_tf32(v.w);
        o[i] = v;
    }
}

// ---------------- tf32 mma.sync GEMM: C[M,512] = A[M,K] @ Wt[512,K]^T -------
// 128x128 CTA tile, 8 warps (64x32 warp tile), BK=16, 2-stage cp.async.
// Smem rows padded to 20 floats -> fragment LDS is bank-conflict-free.
// EPI: 0 = none, 1 = bias + tanh
#define SROW 20
template <int K, int EPI>
__global__ void __launch_bounds__(256) mma_gemm(const float* __restrict__ A,
                                                const float* __restrict__ Bt,
                                                const float* __restrict__ bias,
                                                float* __restrict__ C) {
    constexpr int NT = K / 16;
    __shared__ float As[2][128 * SROW];
    __shared__ float Bs[2][128 * SROW];
    int tid = threadIdx.x;
    int wid = tid >> 5, lane = tid & 31;
    int g = lane >> 2, q = lane & 3;
    int wm = wid >> 2, wn = wid & 3;
    int m0 = blockIdx.y * 128, n0 = blockIdx.x * 128;

    // global load geometry: 512 float4 per matrix per stage, 2 per thread
    int lr = tid >> 2;   // 0..63
    int lc = tid & 3;    // float4 index within 16-float row
    const float* Ag0 = A + (size_t)(m0 + lr) * K + lc * 4;
    const float* Ag1 = A + (size_t)(m0 + lr + 64) * K + lc * 4;
    const float* Bg0 = Bt + (size_t)(n0 + lr) * K + lc * 4;
    const float* Bg1 = Bt + (size_t)(n0 + lr + 64) * K + lc * 4;
    uint32_t sa0 = s2u(&As[0][lr * SROW + lc * 4]);
    uint32_t sa1 = s2u(&As[0][(lr + 64) * SROW + lc * 4]);
    uint32_t sb0 = s2u(&Bs[0][lr * SROW + lc * 4]);
    uint32_t sb1 = s2u(&Bs[0][(lr + 64) * SROW + lc * 4]);
    const uint32_t STB = 128 * SROW * 4;   // bytes per stage

    auto load_stage = [&](int kt, int st) {
        uint32_t o = st * STB;
        cp16(sa0 + o, Ag0 + kt * 16);
        cp16(sa1 + o, Ag1 + kt * 16);
        cp16(sb0 + o, Bg0 + kt * 16);
        cp16(sb1 + o, Bg1 + kt * 16);
        asm volatile("cp.async.commit_group;" ::: "memory");
    };

    float acc[4][4][4];
#pragma unroll
    for (int i = 0; i < 4; ++i)
#pragma unroll
        for (int j = 0; j < 4; ++j)
#pragma unroll
            for (int t = 0; t < 4; ++t) acc[i][j][t] = 0.f;

    load_stage(0, 0);
    if (NT > 1) load_stage(1, 1);

#pragma unroll 1
    for (int kt = 0; kt < NT; ++kt) {
        int st = kt & 1;
        if (kt + 1 < NT) asm volatile("cp.async.wait_group 1;" ::: "memory");
        else             asm volatile("cp.async.wait_group 0;" ::: "memory");
        __syncthreads();

        const float* as = As[st];
        const float* bs = Bs[st];
#pragma unroll
        for (int ks = 0; ks < 2; ++ks) {
            int k0 = ks * 8;
            uint32_t af[4][4], bf[4][2];
#pragma unroll
            for (int mi = 0; mi < 4; ++mi) {
                const float* ap = as + (wm * 64 + mi * 16 + g) * SROW + k0 + q;
                af[mi][0] = __float_as_uint(ap[0]);
                af[mi][1] = __float_as_uint(ap[8 * SROW]);
                af[mi][2] = __float_as_uint(ap[4]);
                af[mi][3] = __float_as_uint(ap[8 * SROW + 4]);
            }
#pragma unroll
            for (int ni = 0; ni < 4; ++ni) {
                const float* bp = bs + (wn * 32 + ni * 8 + g) * SROW + k0 + q;
                bf[ni][0] = __float_as_uint(bp[0]);
                bf[ni][1] = __float_as_uint(bp[4]);
            }
#pragma unroll
            for (int mi = 0; mi < 4; ++mi)
#pragma unroll
                for (int ni = 0; ni < 4; ++ni)
                    mma_tf32_16n8k8(acc[mi][ni], af[mi], bf[ni]);
        }
        __syncthreads();
        if (kt + 2 < NT) load_stage(kt + 2, st);
    }

    // epilogue: c0,c1 at (row g, col 2q,2q+1); c2,c3 at (row g+8)
#pragma unroll
    for (int mi = 0; mi < 4; ++mi) {
        int row0 = m0 + wm * 64 + mi * 16 + g;
#pragma unroll
        for (int ni = 0; ni < 4; ++ni) {
            int col = n0 + wn * 32 + ni * 8 + 2 * q;
            float2 v0 = make_float2(acc[mi][ni][0], acc[mi][ni][1]);
            float2 v1 = make_float2(acc[mi][ni][2], acc[mi][ni][3]);
            if (EPI == 1) {
                float2 bb = *(const float2*)(bias + col);
                v0.x = tanhf(v0.x + bb.x); v0.y = tanhf(v0.y + bb.y);
                v1.x = tanhf(v1.x + bb.x); v1.y = tanhf(v1.y + bb.y);
            }
            *(float2*)(C + (size_t)row0 * HID + col) = v0;
            *(float2*)(C + (size_t)(row0 + 8) * HID + col) = v1;
        }
    }
}

// ---------------- fp32 tiled SGEMM (head only) ------------------------------
template <int EPI>
__global__ void sgemm(const float* __restrict__ A, const float* __restrict__ B,
                      const float* __restrict__ bias, float* __restrict__ C,
                      int M, int N, int K) {
    __shared__ float As[8][128];
    __shared__ float Bs[8][128];
    int tid = threadIdx.x;
    int m0 = blockIdx.y * 128;
    int n0 = blockIdx.x * 128;
    int arow = tid >> 1;
    int acol = (tid & 1) * 4;
    int brow = tid >> 5;
    int bcol = (tid & 31) * 4;
    int ty = tid >> 4;
    int tx = tid & 15;
    float acc[8][8] = {};

    for (int k0 = 0; k0 < K; k0 += 8) {
        float4 av = *(const float4*)(A + (size_t)(m0 + arow) * K + k0 + acol);
        As[acol + 0][arow] = av.x;
        As[acol + 1][arow] = av.y;
        As[acol + 2][arow] = av.z;
        As[acol + 3][arow] = av.w;
        *(float4*)(&Bs[brow][bcol]) =
            *(const float4*)(B + (size_t)(k0 + brow) * N + n0 + bcol);
        __syncthreads();
#pragma unroll
        for (int k = 0; k < 8; ++k) {
            float a[8], b[8];
            *(float4*)(a) = *(float4*)(&As[k][ty * 8]);
            *(float4*)(a + 4) = *(float4*)(&As[k][ty * 8 + 4]);
            *(float4*)(b) = *(float4*)(&Bs[k][tx * 8]);
            *(float4*)(b + 4) = *(float4*)(&Bs[k][tx * 8 + 4]);
#pragma unroll
            for (int i = 0; i < 8; ++i)
#pragma unroll
                for (int j = 0; j < 8; ++j) acc[i][j] = fmaf(a[i], b[j], acc[i][j]);
        }
        __syncthreads();
    }
#pragma unroll
    for (int i = 0; i < 8; ++i) {
        int row = m0 + ty * 8 + i;
#pragma unroll
        for (int j = 0; j < 8; j += 4) {
            int col = n0 + tx * 8 + j;
            float4 v = make_float4(acc[i][j], acc[i][j + 1], acc[i][j + 2], acc[i][j + 3]);
            if (EPI != 0) {
                float4 bb = *(const float4*)(bias + col);
                v.x += bb.x; v.y += bb.y; v.z += bb.z; v.w += bb.w;
                if (EPI == 1) {
                    v.x = tanhf(v.x); v.y = tanhf(v.y); v.z = tanhf(v.z); v.w = tanhf(v.w);
                } else {
                    v.x = fmaxf(v.x, 0.f); v.y = fmaxf(v.y, 0.f);
                    v.z = fmaxf(v.z, 0.f); v.w = fmaxf(v.w, 0.f);
                }
            }
            *(float4*)(C + (size_t)row * N + col) = v;
        }
    }
}

// ---------------- per-graph dense aggregation: H = A_g @ T_g + b ------------
// output rounded to tf32 (feeds next MMA)
#define AGG_SMEM ((50 * 100 + 100 * 512) * 4)
__global__ void k_agg(const float* __restrict__ T, const float* __restrict__ bias,
                      float* __restrict__ Hout) {
    extern __shared__ float sh[];
    float* Ash = sh;
    float* Tsh = sh + 5000;
    int g = blockIdx.x, rh = blockIdx.y;
    int tid = threadIdx.x;

    const float* Ag = d_A + g * NPG * NPG + rh * 50 * NPG;
    for (int i = tid; i < 5000; i += 128) Ash[i] = Ag[i];
    const float4* Tg = (const float4*)(T + (size_t)g * NPG * HID);
    float4* T4 = (float4*)Tsh;
    for (int i = tid; i < NPG * 128; i += 128) T4[i] = Tg[i];
    __syncthreads();

    int c = tid * 4;
    float4 bv = *(const float4*)(bias + c);
#pragma unroll 1
    for (int r0 = 0; r0 < 50; r0 += 10) {
        float4 acc[10];
#pragma unroll
        for (int i = 0; i < 10; ++i) acc[i] = make_float4(0.f, 0.f, 0.f, 0.f);
        for (int k = 0; k < NPG; ++k) {
            float4 t = *(float4*)(Tsh + k * HID + c);
#pragma unroll
            for (int i = 0; i < 10; ++i) {
                float a = Ash[(r0 + i) * NPG + k];
                acc[i].x = fmaf(a, t.x, acc[i].x);
                acc[i].y = fmaf(a, t.y, acc[i].y);
                acc[i].z = fmaf(a, t.z, acc[i].z);
                acc[i].w = fmaf(a, t.w, acc[i].w);
            }
        }
#pragma unroll
        for (int i = 0; i < 10; ++i) {
            int row = g * NPG + rh * 50 + r0 + i;
            float4 v = make_float4(rna_tf32(acc[i].x + bv.x), rna_tf32(acc[i].y + bv.y),
                                   rna_tf32(acc[i].z + bv.z), rna_tf32(acc[i].w + bv.w));
            *(float4*)(Hout + (size_t)row * HID + c) = v;
        }
    }
}

// ---------------- assignment: softmax(U @ Wc2 + bc2) ------------------------
__global__ void k_assign(const float* __restrict__ U, const float* __restrict__ Wc2,
                         const float* __restrict__ bc2) {
    __shared__ float w[HID * 2];
    int tid = threadIdx.x;
    for (int i = tid; i < HID * 2; i += 128) w[i] = Wc2[i];
    __syncthreads();
    int warp = tid >> 5, lane = tid & 31;
    int n = blockIdx.x * 4 + warp;
    const float* u = U + (size_t)n * HID;
    float s0 = 0.f, s1 = 0.f;
    for (int k = lane; k < HID; k += 32) {
        float uv = u[k];
        s0 = fmaf(uv, w[2 * k], s0);
        s1 = fmaf(uv, w[2 * k + 1], s1);
    }
#pragma unroll
    for (int o = 16; o > 0; o >>= 1) {
        s0 += __shfl_xor_sync(0xffffffff, s0, o);
        s1 += __shfl_xor_sync(0xffffffff, s1, o);
    }
    if (lane == 0) {
        float z0 = s0 + bc2[0], z1 = s1 + bc2[1];
        float m = fmaxf(z0, z1);
        float e0 = expf(z0 - m), e1 = expf(z1 - m);
        float inv = 1.f / (e0 + e1);
        d_assign[n * 2] = e0 * inv;
        d_assign[n * 2 + 1] = e1 * inv;
    }
}

// ---------------- pos + global h column sums --------------------------------
__global__ void k_pos() {
    __shared__ float a0[NPG];
    int g = blockIdx.x, c = threadIdx.x;
    if (c < NPG) a0[c] = d_assign[(g * NPG + c) * 2];
    __syncthreads();
    const float* h = d_Hb + (size_t)g * NPG * HID;
    float acc = 0.f, gs = 0.f;
    for (int n = 0; n < NPG; ++n) {
        float hv = h[n * HID + c];
        acc = fmaf(a0[n], hv, acc);
        gs += hv;
    }
    d_pos[g * HID + c] = acc;
    atomicAdd(&d_gvec[c], gs);
}

// ---------------- new_adj + penalty ----------------------------------------
__global__ void k_newadj(const int* __restrict__ ei) {
    __shared__ float sa[NPG * 2];
    __shared__ float red[4][4];
    int g = blockIdx.x, tid = threadIdx.x;
    if (tid < NPG * 2) sa[tid] = d_assign[g * NPG * 2 + tid];
    __syncthreads();
    float a00 = 0, a01 = 0, a10 = 0, a11 = 0;
    for (int e = tid; e < EPG; e += 128) {
        int s = ei[g * EPG + e] - g * NPG;
        int d = ei[N_EDGES + g * EPG + e] - g * NPG;
        float s0 = sa[2 * s], s1 = sa[2 * s + 1];
        float t0 = sa[2 * d], t1 = sa[2 * d + 1];
        a00 = fmaf(s0, t0, a00); a01 = fmaf(s0, t1, a01);
        a10 = fmaf(s1, t0, a10); a11 = fmaf(s1, t1, a11);
    }
#pragma unroll
    for (int o = 16; o > 0; o >>= 1) {
        a00 += __shfl_xor_sync(0xffffffff, a00, o);
        a01 += __shfl_xor_sync(0xffffffff, a01, o);
        a10 += __shfl_xor_sync(0xffffffff, a10, o);
        a11 += __shfl_xor_sync(0xffffffff, a11, o);
    }
    int warp = tid >> 5, lane = tid & 31;
    if (lane == 0) {
        red[warp][0] = a00; red[warp][1] = a01;
        red[warp][2] = a10; red[warp][3] = a11;
    }
    __syncthreads();
    if (tid < 4) {
        float v = red[0][tid] + red[1][tid] + red[2][tid] + red[3][tid];
        d_newadj[g * 4 + tid] = v;
    }
}

__global__ void k_penalty(float* __restrict__ out) {
    __shared__ float red[NG];
    int g = threadIdx.x;
    float a00 = d_newadj[g * 4], a01 = d_newadj[g * 4 + 1];
    float a10 = d_newadj[g * 4 + 2], a11 = d_newadj[g * 4 + 3];
    float r0 = fmaxf(fabsf(a00) + fabsf(a01), EPSV);
    float r1 = fmaxf(fabsf(a10) + fabsf(a11), EPSV);
    float dd0 = a00 / r0 - 1.f, dd1 = a11 / r1 - 1.f;
    red[g] = dd0 * dd0 + dd1 * dd1;
    __syncthreads();
    for (int s = 256; s > 0; s >>= 1) {
        if (g < s) red[g] += red[g + s];
        __syncthreads();
    }
    if (g == 0) out[OUT_PEN] = red[0] * (1.f / (NG * 2.f));
}

// ---------------- norm reductions ------------------------------------------
__global__ void k_sumsq_pos() {
    __shared__ float red[256];
    int tid = threadIdx.x;
    float s = 0.f;
    for (int i = blockIdx.x * 256 + tid; i < NG * HID; i += gridDim.x * 256) {
        float v = d_pos[i];
        s = fmaf(v, v, s);
    }
    red[tid] = s;
    __syncthreads();
    for (int o = 128; o > 0; o >>= 1) {
        if (tid < o) red[tid] += red[tid + o];
        __syncthreads();
    }
    if (tid == 0) atomicAdd(&d_scal[0], red[0]);
}

__global__ void k_pg() {
    __shared__ float red[HID];
    int t = threadIdx.x;
    float v = d_gvec[t] * (1.f / (float)N_NODES);
    red[t] = v * v;
    __syncthreads();
    for (int s = 256; s > 0; s >>= 1) {
        if (t < s) red[t] += red[t + s];
        __syncthreads();
    }
    if (t == 0) d_scal[1] = red[0] * (1.f / (float)HID);
}

__global__ void k_finpos(float* __restrict__ out) {
    int i = blockIdx.x * blockDim.x + threadIdx.x;
    if (i < NG * HID) {
        float ms = d_scal[0] * (1.f / (float)(NG * HID));
        float sc = (ms > 1.f) ? rsqrtf(ms) : 1.f;
        float v = d_pos[i] * sc;
        d_pos[i] = v;
        out[OUT_POS + i] = v;
    }
}

__global__ void k_fingemb(float* __restrict__ out) {
    int i = blockIdx.x * blockDim.x + threadIdx.x;
    if (i < NG * HID) {
        float ms = d_scal[1];
        float sc = (ms > 1.f) ? rsqrtf(ms) : 1.f;
        float v = d_gvec[i & (HID - 1)] * (1.f / (float)N_NODES) * sc;
        out[OUT_GEMB + i] = v;
    }
}

// ---------------- head ------------------------------------------------------
__global__ void k_head(const float* __restrict__ Z, const float* __restrict__ Wl2,
                       const float* __restrict__ bl2, float* __restrict__ out) {
    __shared__ float w[HID * 6];
    int tid = threadIdx.x;
    for (int i = tid; i < HID * 6; i += 128) w[i] = Wl2[i];
    __syncthreads();
    int warp = tid >> 5, lane = tid & 31;
    int row = blockIdx.x * 4 + warp;
    const float* z = Z + (size_t)row * HID;
    float s[6] = {0, 0, 0, 0, 0, 0};
    for (int k = lane; k < HID; k += 32) {
        float zv = z[k];
#pragma unroll
        for (int j = 0; j < 6; ++j) s[j] = fmaf(zv, w[k * 6 + j], s[j]);
    }
#pragma unroll
    for (int o = 16; o > 0; o >>= 1)
#pragma unroll
        for (int j = 0; j < 6; ++j) s[j] += __shfl_xor_sync(0xffffffff, s[j], o);
    if (lane == 0) {
        float o6[6], m = -1e30f;
#pragma unroll
        for (int j = 0; j < 6; ++j) { o6[j] = s[j] + bl2[j]; m = fmaxf(m, o6[j]); }
        float sum = 0.f;
#pragma unroll
        for (int j = 0; j < 6; ++j) sum += expf(o6[j] - m);
        float lse = m + logf(sum);
#pragma unroll
        for (int j = 0; j < 6; ++j) out[OUT_LOGP + row * 6 + j] = o6[j] - lse;
    }
}

// ---------------- launch ----------------------------------------------------
extern "C" void kernel_launch(void* const* d_in, const int* in_sizes, int n_in,
                              void* d_out, int out_size) {
    const float* x   = (const float*)d_in[0];
    const int*   ei  = (const int*)d_in[1];
    const float* W1  = (const float*)d_in[4];
    const float* b1  = (const float*)d_in[5];
    const float* W2  = (const float*)d_in[6];
    const float* b2  = (const float*)d_in[7];
    const float* W3  = (const float*)d_in[8];
    const float* b3  = (const float*)d_in[9];
    const float* Wc1 = (const float*)d_in[10];
    const float* bc1 = (const float*)d_in[11];
    const float* Wc2 = (const float*)d_in[12];
    const float* bc2 = (const float*)d_in[13];
    const float* Wl1 = (const float*)d_in[14];
    const float* bl1 = (const float*)d_in[15];
    const float* Wl2 = (const float*)d_in[16];
    const float* bl2 = (const float*)d_in[17];
    float* out = (float*)d_out;

    float *pT, *pH, *pPos, *pWt;
    cudaGetSymbolAddress((void**)&pT, d_T);
    cudaGetSymbolAddress((void**)&pH, d_Hb);
    cudaGetSymbolAddress((void**)&pPos, d_pos);
    cudaGetSymbolAddress((void**)&pWt, d_Wt);

    cudaFuncSetAttribute(k_agg, cudaFuncAttributeMaxDynamicSharedMemorySize, AGG_SMEM);

    float* Wt0 = pWt;
    float* Wt1 = pWt + HID * HID;
    float* Wt2 = pWt + 2 * HID * HID;
    float* Wt3 = pWt + 3 * HID * HID;

    // graph structure
    k_zero_misc<<<200, 256>>>();
    k_zeroA<<<20000, 256>>>();
    k_deg<<<3200, 256>>>(ei);
    k_dis<<<200, 256>>>();
    k_diag<<<200, 256>>>();
    k_edgeA<<<3200, 256>>>(ei);

    // weight transposes (+ tf32 rounding)
    dim3 tb(32, 8);
    k_transpose<<<dim3(HID / 32, FIN / 32), tb>>>(W1, Wt0, FIN, HID);
    k_transpose<<<dim3(HID / 32, HID / 32), tb>>>(W2, Wt1, HID, HID);
    k_transpose<<<dim3(HID / 32, HID / 32), tb>>>(W3, Wt2, HID, HID);
    k_transpose<<<dim3(HID / 32, HID / 32), tb>>>(Wc1, Wt3, HID, HID);
    k_round_x<<<(N_NODES * FIN / 4 + 255) / 256, 256>>>((const float4*)x, (float4*)pH);

    dim3 gBig(HID / 128, N_NODES / 128);
    dim3 gAgg(NG, 2);

    // 3 GCN layers: T = H@W (tensor core tf32) ; H = A_hat @ T + b (rounded)
    mma_gemm<FIN, 0><<<gBig, 256>>>(pH, Wt0, nullptr, pT);
    k_agg<<<gAgg, 128, AGG_SMEM>>>(pT, b1, pH);
    mma_gemm<HID, 0><<<gBig, 256>>>(pH, Wt1, nullptr, pT);
    k_agg<<<gAgg, 128, AGG_SMEM>>>(pT, b2, pH);
    mma_gemm<HID, 0><<<gBig, 256>>>(pH, Wt2, nullptr, pT);
    k_agg<<<gAgg, 128, AGG_SMEM>>>(pT, b3, pH);

    // assignment = softmax(tanh(h@Wc1+bc1)@Wc2+bc2)
    mma_gemm<HID, 1><<<gBig, 256>>>(pH, Wt3, bc1, pT);
    k_assign<<<N_NODES / 4, 128>>>(pT, Wc2, bc2);

    // pooling / penalty
    k_pos<<<NG, HID>>>();
    k_newadj<<<NG, 128>>>(ei);
    k_penalty<<<1, NG>>>(out);

    // normalizations
    k_sumsq_pos<<<256, 256>>>();
    k_pg<<<1, HID>>>();
    k_finpos<<<1024, 256>>>(out);
    k_fingemb<<<1024, 256>>>(out);

    // head MLP on normalized pos
    dim3 gHead(HID / 128, NG / 128);
    sgemm<2><<<gHead, 256>>>(pPos, Wl1, bl1, pT, NG, HID, HID);
    k_head<<<NG / 4, 128>>>(pT, Wl2, bl2, out);
}

// round 5
// speedup vs baseline: 3.3309x; 1.9548x over previous
#include <cuda_runtime.h>
#include <cuda_fp16.h>
#include <math.h>
#include <cstdint>

#define N_NODES 51200
#define N_EDGES 819200
#define NG 512
#define NPG 100
#define EPG 1600
#define HID 512
#define FIN 128
#define EPSV 1e-5f

#define OUT_LOGP 0
#define OUT_POS 3072
#define OUT_GEMB 265216
#define OUT_PEN 527360

// ---------------- scratch (static device allocations; no cudaMalloc) --------
__device__ float d_deg[N_NODES];
__device__ float d_dis[N_NODES];
__device__ float d_A[NG * NPG * NPG];
__device__ __half d_Ah[NG * 128 * 120];        // padded half adjacency [g][m:128][k:120]
__device__ __half d_Th[N_NODES * HID];         // GEMM output (half)
__device__ __half d_Hh[N_NODES * HID];         // agg output (half) -> next GEMM
__device__ __half d_Xh[N_NODES * FIN];         // x in half
__device__ __half d_Wh[4][HID * HID];          // transposed half weights [N][K]
__device__ float d_Hb[N_NODES * HID];          // fp32 h (last layer only, pooling)
__device__ float d_T[N_NODES * HID];           // fp32 scratch (head path)
__device__ float d_assign[N_NODES * 2];
__device__ float d_pos[NG * HID];
__device__ float d_gvec[HID];
__device__ float d_newadj[NG * 4];
__device__ float d_scal[4];

// ---------------- ptx helpers ----------------------------------------------
__device__ __forceinline__ uint32_t s2u(const void* p) {
    uint32_t a;
    asm("{ .reg .u64 t; cvta.to.shared.u64 t, %1; cvt.u32.u64 %0, t; }"
        : "=r"(a) : "l"(p));
    return a;
}
__device__ __forceinline__ void cp16(uint32_t s, const void* g) {
    asm volatile("cp.async.cg.shared.global [%0], [%1], 16;" :: "r"(s), "l"(g));
}
__device__ __forceinline__ void mma_f16(float* c, const uint32_t* a, const uint32_t* b) {
    asm volatile(
        "mma.sync.aligned.m16n8k16.row.col.f32.f16.f16.f32 "
        "{%0,%1,%2,%3}, {%4,%5,%6,%7}, {%8,%9}, {%0,%1,%2,%3};"
        : "+f"(c[0]), "+f"(c[1]), "+f"(c[2]), "+f"(c[3])
        : "r"(a[0]), "r"(a[1]), "r"(a[2]), "r"(a[3]), "r"(b[0]), "r"(b[1]));
}

// ---------------- setup kernels --------------------------------------------
__global__ void k_zero_misc() {
    int i = blockIdx.x * blockDim.x + threadIdx.x;
    if (i < N_NODES) d_deg[i] = 0.f;
    if (i < HID) d_gvec[i] = 0.f;
    if (i < 4) d_scal[i] = 0.f;
}
__global__ void k_zeroA() {
    int i = blockIdx.x * blockDim.x + threadIdx.x;
    if (i < NG * NPG * NPG) d_A[i] = 0.f;
}
__global__ void k_deg(const int* __restrict__ ei) {
    int e = blockIdx.x * blockDim.x + threadIdx.x;
    if (e < N_EDGES) atomicAdd(&d_deg[ei[N_EDGES + e]], 1.0f);
}
__global__ void k_dis() {
    int i = blockIdx.x * blockDim.x + threadIdx.x;
    if (i < N_NODES) d_dis[i] = rsqrtf(d_deg[i] + 1.0f);
}
__global__ void k_diag() {
    int i = blockIdx.x * blockDim.x + threadIdx.x;
    if (i < N_NODES) {
        int g = i / NPG, l = i % NPG;
        d_A[g * NPG * NPG + l * NPG + l] = d_dis[i] * d_dis[i];
    }
}
__global__ void k_edgeA(const int* __restrict__ ei) {
    int e = blockIdx.x * blockDim.x + threadIdx.x;
    if (e < N_EDGES) {
        int s = ei[e];
        int d = ei[N_EDGES + e];
        float w = d_dis[s] * d_dis[d];
        int g = d / NPG;
        atomicAdd(&d_A[g * NPG * NPG + (d % NPG) * NPG + (s % NPG)], w);
    }
}
// pack fp32 A into zero-padded half [g][128][120]
__global__ void k_A2h() {
    int i = blockIdx.x * blockDim.x + threadIdx.x;
    if (i < NG * 128 * 120) {
        int g = i / (128 * 120);
        int r = (i / 120) & 127;
        int k = i % 120;
        float v = (r < NPG && k < NPG) ? d_A[g * NPG * NPG + r * NPG + k] : 0.f;
        d_Ah[i] = __float2half_rn(v);
    }
}

// ---------------- weight transpose to half: Wt[n][k] = h(W[k][n]) -----------
__global__ void k_transpose_h(const float* __restrict__ W, __half* __restrict__ Wt,
                              int K, int N) {
    __shared__ float tile[32][33];
    int k0 = blockIdx.y * 32, n0 = blockIdx.x * 32;
    int tx = threadIdx.x, ty = threadIdx.y;  // 32 x 8
    for (int j = ty; j < 32; j += 8) tile[j][tx] = W[(size_t)(k0 + j) * N + n0 + tx];
    __syncthreads();
    for (int j = ty; j < 32; j += 8)
        Wt[(size_t)(n0 + j) * K + k0 + tx] = __float2half_rn(tile[tx][j]);
}

__global__ void k_x2h(const float2* __restrict__ x, __half2* __restrict__ o) {
    int i = blockIdx.x * blockDim.x + threadIdx.x;
    if (i < N_NODES * FIN / 2) o[i] = __float22half2_rn(x[i]);
}

// ---------------- fp16 mma GEMM: C[M,512] = A[M,K] @ Wt[512,K]^T ------------
// 128x128 CTA tile, 8 warps (64x32 warp tile), BK=32, 2-stage cp.async.
// Smem rows padded to 40 halves -> fragment LDS conflict-free.
// EPI: 0 = plain half out, 1 = bias + tanh half out
template <int K, int EPI>
__global__ void __launch_bounds__(256) hgemm(const __half* __restrict__ A,
                                             const __half* __restrict__ Bt,
                                             const float* __restrict__ bias,
                                             __half* __restrict__ C) {
    constexpr int NT = K / 32;
    __shared__ __half As[2][128 * 40];
    __shared__ __half Bs[2][128 * 40];
    int tid = threadIdx.x;
    int wid = tid >> 5, lane = tid & 31;
    int g = lane >> 2, q = lane & 3;
    int wm = wid >> 2, wn = wid & 3;
    int m0 = blockIdx.y * 128, n0 = blockIdx.x * 128;

    int lr = tid >> 1, lc = tid & 1;   // row 0..127, half-row chunk 0..1
    const __half* Ag = A + (size_t)(m0 + lr) * K + lc * 16;
    const __half* Bg = Bt + (size_t)(n0 + lr) * K + lc * 16;
    uint32_t sa = s2u(&As[0][lr * 40 + lc * 16]);
    uint32_t sb = s2u(&Bs[0][lr * 40 + lc * 16]);
    const uint32_t STB = 128 * 40 * 2;

    auto load_stage = [&](int kt, int st) {
        uint32_t o = st * STB;
        cp16(sa + o, Ag + kt * 32);
        cp16(sa + o + 16, Ag + kt * 32 + 8);
        cp16(sb + o, Bg + kt * 32);
        cp16(sb + o + 16, Bg + kt * 32 + 8);
        asm volatile("cp.async.commit_group;" ::: "memory");
    };

    float acc[4][4][4];
#pragma unroll
    for (int i = 0; i < 4; ++i)
#pragma unroll
        for (int j = 0; j < 4; ++j)
#pragma unroll
            for (int t = 0; t < 4; ++t) acc[i][j][t] = 0.f;

    load_stage(0, 0);
    if (NT > 1) load_stage(1, 1);

#pragma unroll 1
    for (int kt = 0; kt < NT; ++kt) {
        int st = kt & 1;
        if (kt + 1 < NT) asm volatile("cp.async.wait_group 1;" ::: "memory");
        else             asm volatile("cp.async.wait_group 0;" ::: "memory");
        __syncthreads();

        const __half* as = As[st];
        const __half* bs = Bs[st];
#pragma unroll
        for (int ks = 0; ks < 2; ++ks) {
            int k0 = ks * 16;
            uint32_t af[4][4], bf[4][2];
#pragma unroll
            for (int mi = 0; mi < 4; ++mi) {
                const __half* ap = as + (wm * 64 + mi * 16 + g) * 40 + k0 + 2 * q;
                af[mi][0] = *(const uint32_t*)ap;
                af[mi][1] = *(const uint32_t*)(ap + 8 * 40);
                af[mi][2] = *(const uint32_t*)(ap + 8);
                af[mi][3] = *(const uint32_t*)(ap + 8 * 40 + 8);
            }
#pragma unroll
            for (int ni = 0; ni < 4; ++ni) {
                const __half* bp = bs + (wn * 32 + ni * 8 + g) * 40 + k0 + 2 * q;
                bf[ni][0] = *(const uint32_t*)bp;
                bf[ni][1] = *(const uint32_t*)(bp + 8);
            }
#pragma unroll
            for (int mi = 0; mi < 4; ++mi)
#pragma unroll
                for (int ni = 0; ni < 4; ++ni)
                    mma_f16(acc[mi][ni], af[mi], bf[ni]);
        }
        __syncthreads();
        if (kt + 2 < NT) load_stage(kt + 2, st);
    }

#pragma unroll
    for (int mi = 0; mi < 4; ++mi) {
        int row0 = m0 + wm * 64 + mi * 16 + g;
#pragma unroll
        for (int ni = 0; ni < 4; ++ni) {
            int col = n0 + wn * 32 + ni * 8 + 2 * q;
            float v0 = acc[mi][ni][0], v1 = acc[mi][ni][1];
            float v2 = acc[mi][ni][2], v3 = acc[mi][ni][3];
            if (EPI == 1) {
                float2 bb = *(const float2*)(bias + col);
                v0 = tanhf(v0 + bb.x); v1 = tanhf(v1 + bb.y);
                v2 = tanhf(v2 + bb.x); v3 = tanhf(v3 + bb.y);
            }
            *(half2*)(C + (size_t)row0 * HID + col) = __floats2half2_rn(v0, v1);
            *(half2*)(C + (size_t)(row0 + 8) * HID + col) = __floats2half2_rn(v2, v3);
        }
    }
}

// ---------------- tensor-core agg: H = A_g @ T_g + b ------------------------
// grid (NG, 4): graph x 128-col chunk. 8 warps as 4x2 (32x64 warp tile).
// Ash [128 m][120 k] half, Ts [128 n][120 k] half (transposed T chunk).
#define AGGH_SMEM (2 * 128 * 120 * 2)
template <bool WF32>
__global__ void __launch_bounds__(256) k_aggh(const __half* __restrict__ T,
                                              const float* __restrict__ bias,
                                              __half* __restrict__ Hh,
                                              float* __restrict__ Hf) {
    extern __shared__ __half aggsh[];
    __half* Ash = aggsh;              // 128*120
    __half* Ts = aggsh + 128 * 120;   // 128*120
    int gph = blockIdx.x;
    int cb = blockIdx.y * 128;
    int tid = threadIdx.x;
    int wid = tid >> 5, lane = tid & 31;
    int g = lane >> 2, q = lane & 3;
    int wm = wid >> 1, wn = wid & 1;

    // A tile: straight 16B copy (already padded with zeros)
    const uint4* Asrc = (const uint4*)(d_Ah + (size_t)gph * 128 * 120);
    uint4* Adst = (uint4*)Ash;
    for (int i = tid; i < 128 * 120 / 8; i += 256) Adst[i] = Asrc[i];

    // T chunk, transposed: Ts[n][k] = T[(g*100+k)*512 + cb + n]
    const __half* Tg = T + (size_t)gph * NPG * HID + cb;
    for (int i = tid; i < NPG * 128; i += 256) {
        int k = i >> 7, n = i & 127;
        Ts[n * 120 + k] = Tg[(size_t)k * HID + n];
    }
    for (int i = tid; i < 128 * 12; i += 256) {   // zero k pad 100..111
        int n = i / 12, k = NPG + i % 12;
        Ts[n * 120 + k] = __float2half(0.f);
    }
    __syncthreads();

    float acc[2][8][4];
#pragma unroll
    for (int i = 0; i < 2; ++i)
#pragma unroll
        for (int j = 0; j < 8; ++j)
#pragma unroll
            for (int t = 0; t < 4; ++t) acc[i][j][t] = 0.f;

#pragma unroll
    for (int k0 = 0; k0 < 112; k0 += 16) {
        uint32_t af[2][4], bf[8][2];
#pragma unroll
        for (int mi = 0; mi < 2; ++mi) {
            const __half* ap = Ash + (wm * 32 + mi * 16 + g) * 120 + k0 + 2 * q;
            af[mi][0] = *(const uint32_t*)ap;
            af[mi][1] = *(const uint32_t*)(ap + 8 * 120);
            af[mi][2] = *(const uint32_t*)(ap + 8);
            af[mi][3] = *(const uint32_t*)(ap + 8 * 120 + 8);
        }
#pragma unroll
        for (int ni = 0; ni < 8; ++ni) {
            const __half* bp = Ts + (wn * 64 + ni * 8 + g) * 120 + k0 + 2 * q;
            bf[ni][0] = *(const uint32_t*)bp;
            bf[ni][1] = *(const uint32_t*)(bp + 8);
        }
#pragma unroll
        for (int mi = 0; mi < 2; ++mi)
#pragma unroll
            for (int ni = 0; ni < 8; ++ni)
                mma_f16(acc[mi][ni], af[mi], bf[ni]);
    }

#pragma unroll
    for (int mi = 0; mi < 2; ++mi) {
        int rl = wm * 32 + mi * 16 + g;
#pragma unroll
        for (int ni = 0; ni < 8; ++ni) {
            int col = cb + wn * 64 + ni * 8 + 2 * q;
            float2 bb = *(const float2*)(bias + col);
            if (rl < NPG) {
                float v0 = acc[mi][ni][0] + bb.x, v1 = acc[mi][ni][1] + bb.y;
                size_t off = ((size_t)gph * NPG + rl) * HID + col;
                *(half2*)(Hh + off) = __floats2half2_rn(v0, v1);
                if (WF32) *(float2*)(Hf + off) = make_float2(v0, v1);
            }
            if (rl + 8 < NPG) {
                float v0 = acc[mi][ni][2] + bb.x, v1 = acc[mi][ni][3] + bb.y;
                size_t off = ((size_t)gph * NPG + rl + 8) * HID + col;
                *(half2*)(Hh + off) = __floats2half2_rn(v0, v1);
                if (WF32) *(float2*)(Hf + off) = make_float2(v0, v1);
            }
        }
    }
}

// ---------------- fp32 tiled SGEMM (head only) ------------------------------
template <int EPI>
__global__ void sgemm(const float* __restrict__ A, const float* __restrict__ B,
                      const float* __restrict__ bias, float* __restrict__ C,
                      int M, int N, int K) {
    __shared__ float As[8][128];
    __shared__ float Bs[8][128];
    int tid = threadIdx.x;
    int m0 = blockIdx.y * 128;
    int n0 = blockIdx.x * 128;
    int arow = tid >> 1;
    int acol = (tid & 1) * 4;
    int brow = tid >> 5;
    int bcol = (tid & 31) * 4;
    int ty = tid >> 4;
    int tx = tid & 15;
    float acc[8][8] = {};

    for (int k0 = 0; k0 < K; k0 += 8) {
        float4 av = *(const float4*)(A + (size_t)(m0 + arow) * K + k0 + acol);
        As[acol + 0][arow] = av.x;
        As[acol + 1][arow] = av.y;
        As[acol + 2][arow] = av.z;
        As[acol + 3][arow] = av.w;
        *(float4*)(&Bs[brow][bcol]) =
            *(const float4*)(B + (size_t)(k0 + brow) * N + n0 + bcol);
        __syncthreads();
#pragma unroll
        for (int k = 0; k < 8; ++k) {
            float a[8], b[8];
            *(float4*)(a) = *(float4*)(&As[k][ty * 8]);
            *(float4*)(a + 4) = *(float4*)(&As[k][ty * 8 + 4]);
            *(float4*)(b) = *(float4*)(&Bs[k][tx * 8]);
            *(float4*)(b + 4) = *(float4*)(&Bs[k][tx * 8 + 4]);
#pragma unroll
            for (int i = 0; i < 8; ++i)
#pragma unroll
                for (int j = 0; j < 8; ++j) acc[i][j] = fmaf(a[i], b[j], acc[i][j]);
        }
        __syncthreads();
    }
#pragma unroll
    for (int i = 0; i < 8; ++i) {
        int row = m0 + ty * 8 + i;
#pragma unroll
        for (int j = 0; j < 8; j += 4) {
            int col = n0 + tx * 8 + j;
            float4 v = make_float4(acc[i][j], acc[i][j + 1], acc[i][j + 2], acc[i][j + 3]);
            if (EPI != 0) {
                float4 bb = *(const float4*)(bias + col);
                v.x += bb.x; v.y += bb.y; v.z += bb.z; v.w += bb.w;
                if (EPI == 1) {
                    v.x = tanhf(v.x); v.y = tanhf(v.y); v.z = tanhf(v.z); v.w = tanhf(v.w);
                } else {
                    v.x = fmaxf(v.x, 0.f); v.y = fmaxf(v.y, 0.f);
                    v.z = fmaxf(v.z, 0.f); v.w = fmaxf(v.w, 0.f);
                }
            }
            *(float4*)(C + (size_t)row * N + col) = v;
        }
    }
}

// ---------------- assignment: softmax(U @ Wc2 + bc2), U in half -------------
__global__ void k_assign(const __half* __restrict__ U, const float* __restrict__ Wc2,
                         const float* __restrict__ bc2) {
    __shared__ float w[HID * 2];
    int tid = threadIdx.x;
    for (int i = tid; i < HID * 2; i += 128) w[i] = Wc2[i];
    __syncthreads();
    int warp = tid >> 5, lane = tid & 31;
    int n = blockIdx.x * 4 + warp;
    const __half* u = U + (size_t)n * HID;
    float s0 = 0.f, s1 = 0.f;
    for (int k = lane; k < HID; k += 32) {
        float uv = __half2float(u[k]);
        s0 = fmaf(uv, w[2 * k], s0);
        s1 = fmaf(uv, w[2 * k + 1], s1);
    }
#pragma unroll
    for (int o = 16; o > 0; o >>= 1) {
        s0 += __shfl_xor_sync(0xffffffff, s0, o);
        s1 += __shfl_xor_sync(0xffffffff, s1, o);
    }
    if (lane == 0) {
        float z0 = s0 + bc2[0], z1 = s1 + bc2[1];
        float m = fmaxf(z0, z1);
        float e0 = expf(z0 - m), e1 = expf(z1 - m);
        float inv = 1.f / (e0 + e1);
        d_assign[n * 2] = e0 * inv;
        d_assign[n * 2 + 1] = e1 * inv;
    }
}

// ---------------- pos + global h column sums --------------------------------
__global__ void k_pos() {
    __shared__ float a0[NPG];
    int g = blockIdx.x, c = threadIdx.x;
    if (c < NPG) a0[c] = d_assign[(g * NPG + c) * 2];
    __syncthreads();
    const float* h = d_Hb + (size_t)g * NPG * HID;
    float acc = 0.f, gs = 0.f;
    for (int n = 0; n < NPG; ++n) {
        float hv = h[n * HID + c];
        acc = fmaf(a0[n], hv, acc);
        gs += hv;
    }
    d_pos[g * HID + c] = acc;
    atomicAdd(&d_gvec[c], gs);
}

// ---------------- new_adj + penalty ----------------------------------------
__global__ void k_newadj(const int* __restrict__ ei) {
    __shared__ float sa[NPG * 2];
    __shared__ float red[4][4];
    int g = blockIdx.x, tid = threadIdx.x;
    if (tid < NPG * 2) sa[tid] = d_assign[g * NPG * 2 + tid];
    __syncthreads();
    float a00 = 0, a01 = 0, a10 = 0, a11 = 0;
    for (int e = tid; e < EPG; e += 128) {
        int s = ei[g * EPG + e] - g * NPG;
        int d = ei[N_EDGES + g * EPG + e] - g * NPG;
        float s0 = sa[2 * s], s1 = sa[2 * s + 1];
        float t0 = sa[2 * d], t1 = sa[2 * d + 1];
        a00 = fmaf(s0, t0, a00); a01 = fmaf(s0, t1, a01);
        a10 = fmaf(s1, t0, a10); a11 = fmaf(s1, t1, a11);
    }
#pragma unroll
    for (int o = 16; o > 0; o >>= 1) {
        a00 += __shfl_xor_sync(0xffffffff, a00, o);
        a01 += __shfl_xor_sync(0xffffffff, a01, o);
        a10 += __shfl_xor_sync(0xffffffff, a10, o);
        a11 += __shfl_xor_sync(0xffffffff, a11, o);
    }
    int warp = tid >> 5, lane = tid & 31;
    if (lane == 0) {
        red[warp][0] = a00; red[warp][1] = a01;
        red[warp][2] = a10; red[warp][3] = a11;
    }
    __syncthreads();
    if (tid < 4) {
        float v = red[0][tid] + red[1][tid] + red[2][tid] + red[3][tid];
        d_newadj[g * 4 + tid] = v;
    }
}

__global__ void k_penalty(float* __restrict__ out) {
    __shared__ float red[NG];
    int g = threadIdx.x;
    float a00 = d_newadj[g * 4], a01 = d_newadj[g * 4 + 1];
    float a10 = d_newadj[g * 4 + 2], a11 = d_newadj[g * 4 + 3];
    float r0 = fmaxf(fabsf(a00) + fabsf(a01), EPSV);
    float r1 = fmaxf(fabsf(a10) + fabsf(a11), EPSV);
    float dd0 = a00 / r0 - 1.f, dd1 = a11 / r1 - 1.f;
    red[g] = dd0 * dd0 + dd1 * dd1;
    __syncthreads();
    for (int s = 256; s > 0; s >>= 1) {
        if (g < s) red[g] += red[g + s];
        __syncthreads();
    }
    if (g == 0) out[OUT_PEN] = red[0] * (1.f / (NG * 2.f));
}

// ---------------- norm reductions ------------------------------------------
__global__ void k_sumsq_pos() {
    __shared__ float red[256];
    int tid = threadIdx.x;
    float s = 0.f;
    for (int i = blockIdx.x * 256 + tid; i < NG * HID; i += gridDim.x * 256) {
        float v = d_pos[i];
        s = fmaf(v, v, s);
    }
    red[tid] = s;
    __syncthreads();
    for (int o = 128; o > 0; o >>= 1) {
        if (tid < o) red[tid] += red[tid + o];
        __syncthreads();
    }
    if (tid == 0) atomicAdd(&d_scal[0], red[0]);
}

__global__ void k_pg() {
    __shared__ float red[HID];
    int t = threadIdx.x;
    float v = d_gvec[t] * (1.f / (float)N_NODES);
    red[t] = v * v;
    __syncthreads();
    for (int s = 256; s > 0; s >>= 1) {
        if (t < s) red[t] += red[t + s];
        __syncthreads();
    }
    if (t == 0) d_scal[1] = red[0] * (1.f / (float)HID);
}

__global__ void k_finpos(float* __restrict__ out) {
    int i = blockIdx.x * blockDim.x + threadIdx.x;
    if (i < NG * HID) {
        float ms = d_scal[0] * (1.f / (float)(NG * HID));
        float sc = (ms > 1.f) ? rsqrtf(ms) : 1.f;
        float v = d_pos[i] * sc;
        d_pos[i] = v;
        out[OUT_POS + i] = v;
    }
}

__global__ void k_fingemb(float* __restrict__ out) {
    int i = blockIdx.x * blockDim.x + threadIdx.x;
    if (i < NG * HID) {
        float ms = d_scal[1];
        float sc = (ms > 1.f) ? rsqrtf(ms) : 1.f;
        float v = d_gvec[i & (HID - 1)] * (1.f / (float)N_NODES) * sc;
        out[OUT_GEMB + i] = v;
    }
}

// ---------------- head ------------------------------------------------------
__global__ void k_head(const float* __restrict__ Z, const float* __restrict__ Wl2,
                       const float* __restrict__ bl2, float* __restrict__ out) {
    __shared__ float w[HID * 6];
    int tid = threadIdx.x;
    for (int i = tid; i < HID * 6; i += 128) w[i] = Wl2[i];
    __syncthreads();
    int warp = tid >> 5, lane = tid & 31;
    int row = blockIdx.x * 4 + warp;
    const float* z = Z + (size_t)row * HID;
    float s[6] = {0, 0, 0, 0, 0, 0};
    for (int k = lane; k < HID; k += 32) {
        float zv = z[k];
#pragma unroll
        for (int j = 0; j < 6; ++j) s[j] = fmaf(zv, w[k * 6 + j], s[j]);
    }
#pragma unroll
    for (int o = 16; o > 0; o >>= 1)
#pragma unroll
        for (int j = 0; j < 6; ++j) s[j] += __shfl_xor_sync(0xffffffff, s[j], o);
    if (lane == 0) {
        float o6[6], m = -1e30f;
#pragma unroll
        for (int j = 0; j < 6; ++j) { o6[j] = s[j] + bl2[j]; m = fmaxf(m, o6[j]); }
        float sum = 0.f;
#pragma unroll
        for (int j = 0; j < 6; ++j) sum += expf(o6[j] - m);
        float lse = m + logf(sum);
#pragma unroll
        for (int j = 0; j < 6; ++j) out[OUT_LOGP + row * 6 + j] = o6[j] - lse;
    }
}

// ---------------- launch ----------------------------------------------------
extern "C" void kernel_launch(void* const* d_in, const int* in_sizes, int n_in,
                              void* d_out, int out_size) {
    const float* x   = (const float*)d_in[0];
    const int*   ei  = (const int*)d_in[1];
    const float* W1  = (const float*)d_in[4];
    const float* b1  = (const float*)d_in[5];
    const float* W2  = (const float*)d_in[6];
    const float* b2  = (const float*)d_in[7];
    const float* W3  = (const float*)d_in[8];
    const float* b3  = (const float*)d_in[9];
    const float* Wc1 = (const float*)d_in[10];
    const float* bc1 = (const float*)d_in[11];
    const float* Wc2 = (const float*)d_in[12];
    const float* bc2 = (const float*)d_in[13];
    const float* Wl1 = (const float*)d_in[14];
    const float* bl1 = (const float*)d_in[15];
    const float* Wl2 = (const float*)d_in[16];
    const float* bl2 = (const float*)d_in[17];
    float* out = (float*)d_out;

    float *pT, *pHb, *pPos;
    __half *pTh, *pHh, *pXh, *pWh;
    cudaGetSymbolAddress((void**)&pT, d_T);
    cudaGetSymbolAddress((void**)&pHb, d_Hb);
    cudaGetSymbolAddress((void**)&pPos, d_pos);
    cudaGetSymbolAddress((void**)&pTh, d_Th);
    cudaGetSymbolAddress((void**)&pHh, d_Hh);
    cudaGetSymbolAddress((void**)&pXh, d_Xh);
    cudaGetSymbolAddress((void**)&pWh, d_Wh);

    cudaFuncSetAttribute(k_aggh<false>, cudaFuncAttributeMaxDynamicSharedMemorySize, AGGH_SMEM);
    cudaFuncSetAttribute(k_aggh<true>, cudaFuncAttributeMaxDynamicSharedMemorySize, AGGH_SMEM);

    __half* Wh0 = pWh;
    __half* Wh1 = pWh + HID * HID;
    __half* Wh2 = pWh + 2 * HID * HID;
    __half* Wh3 = pWh + 3 * HID * HID;

    // graph structure
    k_zero_misc<<<200, 256>>>();
    k_zeroA<<<20000, 256>>>();
    k_deg<<<3200, 256>>>(ei);
    k_dis<<<200, 256>>>();
    k_diag<<<200, 256>>>();
    k_edgeA<<<3200, 256>>>(ei);
    k_A2h<<<(NG * 128 * 120 + 255) / 256, 256>>>();

    // weight transposes (fp32 -> half, transposed)
    dim3 tb(32, 8);
    k_transpose_h<<<dim3(HID / 32, FIN / 32), tb>>>(W1, Wh0, FIN, HID);
    k_transpose_h<<<dim3(HID / 32, HID / 32), tb>>>(W2, Wh1, HID, HID);
    k_transpose_h<<<dim3(HID / 32, HID / 32), tb>>>(W3, Wh2, HID, HID);
    k_transpose_h<<<dim3(HID / 32, HID / 32), tb>>>(Wc1, Wh3, HID, HID);
    k_x2h<<<(N_NODES * FIN / 2 + 255) / 256, 256>>>((const float2*)x, (__half2*)pXh);

    dim3 gBig(HID / 128, N_NODES / 128);
    dim3 gAgg(NG, 4);

    // 3 GCN layers: T = H@W (fp16 tensor) ; H = A_hat @ T + b (fp16 tensor)
    hgemm<FIN, 0><<<gBig, 256>>>(pXh, Wh0, nullptr, pTh);
    k_aggh<false><<<gAgg, 256, AGGH_SMEM>>>(pTh, b1, pHh, nullptr);
    hgemm<HID, 0><<<gBig, 256>>>(pHh, Wh1, nullptr, pTh);
    k_aggh<false><<<gAgg, 256, AGGH_SMEM>>>(pTh, b2, pHh, nullptr);
    hgemm<HID, 0><<<gBig, 256>>>(pHh, Wh2, nullptr, pTh);
    k_aggh<true><<<gAgg, 256, AGGH_SMEM>>>(pTh, b3, pHh, pHb);

    // assignment = softmax(tanh(h@Wc1+bc1)@Wc2+bc2)
    hgemm<HID, 1><<<gBig, 256>>>(pHh, Wh3, bc1, pTh);
    k_assign<<<N_NODES / 4, 128>>>(pTh, Wc2, bc2);

    // pooling / penalty
    k_pos<<<NG, HID>>>();
    k_newadj<<<NG, 128>>>(ei);
    k_penalty<<<1, NG>>>(out);

    // normalizations
    k_sumsq_pos<<<256, 256>>>();
    k_pg<<<1, HID>>>();
    k_finpos<<<1024, 256>>>(out);
    k_fingemb<<<1024, 256>>>(out);

    // head MLP on normalized pos (fp32)
    dim3 gHead(HID / 128, NG / 128);
    sgemm<2><<<gHead, 256>>>(pPos, Wl1, bl1, pT, NG, HID, HID);
    k_head<<<NG / 4, 128>>>(pT, Wl2, bl2, out);
}

// round 6
// speedup vs baseline: 3.5916x; 1.0783x over previous
#include <cuda_runtime.h>
#include <cuda_fp16.h>
#include <math.h>
#include <cstdint>

#define N_NODES 51200
#define N_EDGES 819200
#define NG 512
#define NPG 100
#define EPG 1600
#define HID 512
#define FIN 128
#define EPSV 1e-5f

#define OUT_LOGP 0
#define OUT_POS 3072
#define OUT_GEMB 265216
#define OUT_PEN 527360

// ---------------- scratch (static device allocations; no cudaMalloc) --------
__device__ __half d_Ah[NG * 128 * 120];        // padded half adjacency [g][m:128][k:120]
__device__ __half d_Th[N_NODES * HID];         // GEMM output (half)
__device__ __half d_Hh[N_NODES * HID];         // agg output (half)
__device__ __half d_Xh[N_NODES * FIN];         // x in half
__device__ __half d_Wh[4][HID * HID];          // transposed half weights [N][K]
__device__ float d_T[N_NODES * HID];           // fp32 scratch (head path)
__device__ float d_assign[N_NODES * 2];
__device__ float d_pos[NG * HID];
__device__ float d_gvec[HID];
__device__ float d_newadj[NG * 4];
__device__ float d_scal[4];

// ---------------- ptx helpers ----------------------------------------------
__device__ __forceinline__ uint32_t s2u(const void* p) {
    uint32_t a;
    asm("{ .reg .u64 t; cvta.to.shared.u64 t, %1; cvt.u32.u64 %0, t; }"
        : "=r"(a) : "l"(p));
    return a;
}
__device__ __forceinline__ void cp16(uint32_t s, const void* g) {
    asm volatile("cp.async.cg.shared.global [%0], [%1], 16;" :: "r"(s), "l"(g));
}
__device__ __forceinline__ void mma_f16(float* c, const uint32_t* a, const uint32_t* b) {
    asm volatile(
        "mma.sync.aligned.m16n8k16.row.col.f32.f16.f16.f32 "
        "{%0,%1,%2,%3}, {%4,%5,%6,%7}, {%8,%9}, {%0,%1,%2,%3};"
        : "+f"(c[0]), "+f"(c[1]), "+f"(c[2]), "+f"(c[3])
        : "r"(a[0]), "r"(a[1]), "r"(a[2]), "r"(a[3]), "r"(b[0]), "r"(b[1]));
}

// ---------------- fused per-graph structure build ---------------------------
// one block per graph: deg -> dis -> A (fp32 smem) -> padded half write.
__global__ void __launch_bounds__(256) k_build(const int* __restrict__ ei) {
    __shared__ float Adj[NPG * NPG];   // 40000 B
    __shared__ float deg[NPG];
    __shared__ float dis[NPG];
    int g = blockIdx.x, tid = threadIdx.x;
    for (int i = tid; i < NPG * NPG; i += 256) Adj[i] = 0.f;
    if (tid < NPG) deg[tid] = 0.f;
    __syncthreads();
    const int* src = ei + g * EPG;
    const int* dst = ei + N_EDGES + g * EPG;
    int base = g * NPG;
    for (int e = tid; e < EPG; e += 256) atomicAdd(&deg[dst[e] - base], 1.f);
    __syncthreads();
    if (tid < NPG) dis[tid] = rsqrtf(deg[tid] + 1.f);
    __syncthreads();
    for (int e = tid; e < EPG; e += 256) {
        int s = src[e] - base, d = dst[e] - base;
        atomicAdd(&Adj[d * NPG + s], dis[s] * dis[d]);
    }
    __syncthreads();
    if (tid < NPG) Adj[tid * NPG + tid] += dis[tid] * dis[tid];
    __syncthreads();
    __half2* out = (__half2*)(d_Ah + (size_t)g * 128 * 120);
    for (int i = tid; i < 128 * 60; i += 256) {
        int r = i / 60, k = (i % 60) * 2;
        float v0 = (r < NPG && k < NPG) ? Adj[r * NPG + k] : 0.f;
        float v1 = (r < NPG && k + 1 < NPG) ? Adj[r * NPG + k + 1] : 0.f;
        out[i] = __floats2half2_rn(v0, v1);
    }
}

__global__ void k_zero_misc() {   // 1 block x 512
    int i = threadIdx.x;
    d_gvec[i] = 0.f;
    if (i < 4) d_scal[i] = 0.f;
}

// ---------------- weight transpose to half: Wt[n][k] = h(W[k][n]) -----------
__global__ void k_transpose_h(const float* __restrict__ W, __half* __restrict__ Wt,
                              int K, int N) {
    __shared__ float tile[32][33];
    int k0 = blockIdx.y * 32, n0 = blockIdx.x * 32;
    int tx = threadIdx.x, ty = threadIdx.y;  // 32 x 8
    for (int j = ty; j < 32; j += 8) tile[j][tx] = W[(size_t)(k0 + j) * N + n0 + tx];
    __syncthreads();
    for (int j = ty; j < 32; j += 8)
        Wt[(size_t)(n0 + j) * K + k0 + tx] = __float2half_rn(tile[tx][j]);
}

__global__ void k_x2h(const float2* __restrict__ x, __half2* __restrict__ o) {
    int i = blockIdx.x * blockDim.x + threadIdx.x;
    if (i < N_NODES * FIN / 2) o[i] = __float22half2_rn(x[i]);
}

// ---------------- fp16 mma GEMM: C[M,512] = A[M,K] @ Wt[512,K]^T ------------
// 128x128 CTA tile, 8 warps (64x32 warp tile), BK=32, 3-stage cp.async.
// EPI: 0 = plain half out, 1 = bias + tanh half out
#define HG_SMEM (3 * 2 * 128 * 40 * 2)
template <int K, int EPI>
__global__ void __launch_bounds__(256) hgemm(const __half* __restrict__ A,
                                             const __half* __restrict__ Bt,
                                             const float* __restrict__ bias,
                                             __half* __restrict__ C) {
    constexpr int NT = K / 32;
    extern __shared__ __half hsh[];
    __half* As = hsh;                 // 3 x 128*40
    __half* Bs = hsh + 3 * 128 * 40;  // 3 x 128*40
    int tid = threadIdx.x;
    int wid = tid >> 5, lane = tid & 31;
    int g = lane >> 2, q = lane & 3;
    int wm = wid >> 2, wn = wid & 3;
    int m0 = blockIdx.y * 128, n0 = blockIdx.x * 128;

    int lr = tid >> 1, lc = tid & 1;
    const __half* Ag = A + (size_t)(m0 + lr) * K + lc * 16;
    const __half* Bg = Bt + (size_t)(n0 + lr) * K + lc * 16;
    uint32_t sa = s2u(&As[lr * 40 + lc * 16]);
    uint32_t sb = s2u(&Bs[lr * 40 + lc * 16]);
    const uint32_t STB = 128 * 40 * 2;

    auto load_stage = [&](int kt, int st) {
        uint32_t o = st * STB;
        cp16(sa + o, Ag + kt * 32);
        cp16(sa + o + 16, Ag + kt * 32 + 8);
        cp16(sb + o, Bg + kt * 32);
        cp16(sb + o + 16, Bg + kt * 32 + 8);
        asm volatile("cp.async.commit_group;" ::: "memory");
    };

    float acc[4][4][4];
#pragma unroll
    for (int i = 0; i < 4; ++i)
#pragma unroll
        for (int j = 0; j < 4; ++j)
#pragma unroll
            for (int t = 0; t < 4; ++t) acc[i][j][t] = 0.f;

    load_stage(0, 0);
    if (NT > 1) load_stage(1, 1);

#pragma unroll 1
    for (int kt = 0; kt < NT; ++kt) {
        if (kt + 2 < NT) {
            load_stage(kt + 2, (kt + 2) % 3);
            asm volatile("cp.async.wait_group 2;" ::: "memory");
        } else if (kt + 1 < NT) {
            asm volatile("cp.async.wait_group 1;" ::: "memory");
        } else {
            asm volatile("cp.async.wait_group 0;" ::: "memory");
        }
        __syncthreads();

        const __half* as = As + (kt % 3) * 128 * 40;
        const __half* bs = Bs + (kt % 3) * 128 * 40;
#pragma unroll
        for (int ks = 0; ks < 2; ++ks) {
            int k0 = ks * 16;
            uint32_t af[4][4], bf[4][2];
#pragma unroll
            for (int mi = 0; mi < 4; ++mi) {
                const __half* ap = as + (wm * 64 + mi * 16 + g) * 40 + k0 + 2 * q;
                af[mi][0] = *(const uint32_t*)ap;
                af[mi][1] = *(const uint32_t*)(ap + 8 * 40);
                af[mi][2] = *(const uint32_t*)(ap + 8);
                af[mi][3] = *(const uint32_t*)(ap + 8 * 40 + 8);
            }
#pragma unroll
            for (int ni = 0; ni < 4; ++ni) {
                const __half* bp = bs + (wn * 32 + ni * 8 + g) * 40 + k0 + 2 * q;
                bf[ni][0] = *(const uint32_t*)bp;
                bf[ni][1] = *(const uint32_t*)(bp + 8);
            }
#pragma unroll
            for (int mi = 0; mi < 4; ++mi)
#pragma unroll
                for (int ni = 0; ni < 4; ++ni)
                    mma_f16(acc[mi][ni], af[mi], bf[ni]);
        }
        __syncthreads();
    }

#pragma unroll
    for (int mi = 0; mi < 4; ++mi) {
        int row0 = m0 + wm * 64 + mi * 16 + g;
#pragma unroll
        for (int ni = 0; ni < 4; ++ni) {
            int col = n0 + wn * 32 + ni * 8 + 2 * q;
            float v0 = acc[mi][ni][0], v1 = acc[mi][ni][1];
            float v2 = acc[mi][ni][2], v3 = acc[mi][ni][3];
            if (EPI == 1) {
                float2 bb = *(const float2*)(bias + col);
                v0 = tanhf(v0 + bb.x); v1 = tanhf(v1 + bb.y);
                v2 = tanhf(v2 + bb.x); v3 = tanhf(v3 + bb.y);
            }
            *(half2*)(C + (size_t)row0 * HID + col) = __floats2half2_rn(v0, v1);
            *(half2*)(C + (size_t)(row0 + 8) * HID + col) = __floats2half2_rn(v2, v3);
        }
    }
}

// ---------------- tensor-core agg: H = A_g @ T_g + b ------------------------
#define AGGH_SMEM (2 * 128 * 120 * 2)
__global__ void __launch_bounds__(256) k_aggh(const __half* __restrict__ T,
                                              const float* __restrict__ bias,
                                              __half* __restrict__ Hh) {
    extern __shared__ __half aggsh[];
    __half* Ash = aggsh;
    __half* Ts = aggsh + 128 * 120;
    int gph = blockIdx.x;
    int cb = blockIdx.y * 128;
    int tid = threadIdx.x;
    int wid = tid >> 5, lane = tid & 31;
    int g = lane >> 2, q = lane & 3;
    int wm = wid >> 1, wn = wid & 1;

    const uint4* Asrc = (const uint4*)(d_Ah + (size_t)gph * 128 * 120);
    uint4* Adst = (uint4*)Ash;
    for (int i = tid; i < 128 * 120 / 8; i += 256) Adst[i] = Asrc[i];

    const __half* Tg = T + (size_t)gph * NPG * HID + cb;
    for (int i = tid; i < NPG * 128; i += 256) {
        int k = i >> 7, n = i & 127;
        Ts[n * 120 + k] = Tg[(size_t)k * HID + n];
    }
    for (int i = tid; i < 128 * 12; i += 256) {
        int n = i / 12, k = NPG + i % 12;
        Ts[n * 120 + k] = __float2half(0.f);
    }
    __syncthreads();

    float acc[2][8][4];
#pragma unroll
    for (int i = 0; i < 2; ++i)
#pragma unroll
        for (int j = 0; j < 8; ++j)
#pragma unroll
            for (int t = 0; t < 4; ++t) acc[i][j][t] = 0.f;

#pragma unroll
    for (int k0 = 0; k0 < 112; k0 += 16) {
        uint32_t af[2][4], bf[8][2];
#pragma unroll
        for (int mi = 0; mi < 2; ++mi) {
            const __half* ap = Ash + (wm * 32 + mi * 16 + g) * 120 + k0 + 2 * q;
            af[mi][0] = *(const uint32_t*)ap;
            af[mi][1] = *(const uint32_t*)(ap + 8 * 120);
            af[mi][2] = *(const uint32_t*)(ap + 8);
            af[mi][3] = *(const uint32_t*)(ap + 8 * 120 + 8);
        }
#pragma unroll
        for (int ni = 0; ni < 8; ++ni) {
            const __half* bp = Ts + (wn * 64 + ni * 8 + g) * 120 + k0 + 2 * q;
            bf[ni][0] = *(const uint32_t*)bp;
            bf[ni][1] = *(const uint32_t*)(bp + 8);
        }
#pragma unroll
        for (int mi = 0; mi < 2; ++mi)
#pragma unroll
            for (int ni = 0; ni < 8; ++ni)
                mma_f16(acc[mi][ni], af[mi], bf[ni]);
    }

#pragma unroll
    for (int mi = 0; mi < 2; ++mi) {
        int rl = wm * 32 + mi * 16 + g;
#pragma unroll
        for (int ni = 0; ni < 8; ++ni) {
            int col = cb + wn * 64 + ni * 8 + 2 * q;
            float2 bb = *(const float2*)(bias + col);
            if (rl < NPG) {
                size_t off = ((size_t)gph * NPG + rl) * HID + col;
                *(half2*)(Hh + off) =
                    __floats2half2_rn(acc[mi][ni][0] + bb.x, acc[mi][ni][1] + bb.y);
            }
            if (rl + 8 < NPG) {
                size_t off = ((size_t)gph * NPG + rl + 8) * HID + col;
                *(half2*)(Hh + off) =
                    __floats2half2_rn(acc[mi][ni][2] + bb.x, acc[mi][ni][3] + bb.y);
            }
        }
    }
}

// ---------------- fp32 tiled SGEMM (head only) ------------------------------
template <int EPI>
__global__ void sgemm(const float* __restrict__ A, const float* __restrict__ B,
                      const float* __restrict__ bias, float* __restrict__ C,
                      int M, int N, int K) {
    __shared__ float As[8][128];
    __shared__ float Bs[8][128];
    int tid = threadIdx.x;
    int m0 = blockIdx.y * 128;
    int n0 = blockIdx.x * 128;
    int arow = tid >> 1;
    int acol = (tid & 1) * 4;
    int brow = tid >> 5;
    int bcol = (tid & 31) * 4;
    int ty = tid >> 4;
    int tx = tid & 15;
    float acc[8][8] = {};

    for (int k0 = 0; k0 < K; k0 += 8) {
        float4 av = *(const float4*)(A + (size_t)(m0 + arow) * K + k0 + acol);
        As[acol + 0][arow] = av.x;
        As[acol + 1][arow] = av.y;
        As[acol + 2][arow] = av.z;
        As[acol + 3][arow] = av.w;
        *(float4*)(&Bs[brow][bcol]) =
            *(const float4*)(B + (size_t)(k0 + brow) * N + n0 + bcol);
        __syncthreads();
#pragma unroll
        for (int k = 0; k < 8; ++k) {
            float a[8], b[8];
            *(float4*)(a) = *(float4*)(&As[k][ty * 8]);
            *(float4*)(a + 4) = *(float4*)(&As[k][ty * 8 + 4]);
            *(float4*)(b) = *(float4*)(&Bs[k][tx * 8]);
            *(float4*)(b + 4) = *(float4*)(&Bs[k][tx * 8 + 4]);
#pragma unroll
            for (int i = 0; i < 8; ++i)
#pragma unroll
                for (int j = 0; j < 8; ++j) acc[i][j] = fmaf(a[i], b[j], acc[i][j]);
        }
        __syncthreads();
    }
#pragma unroll
    for (int i = 0; i < 8; ++i) {
        int row = m0 + ty * 8 + i;
#pragma unroll
        for (int j = 0; j < 8; j += 4) {
            int col = n0 + tx * 8 + j;
            float4 v = make_float4(acc[i][j], acc[i][j + 1], acc[i][j + 2], acc[i][j + 3]);
            if (EPI != 0) {
                float4 bb = *(const float4*)(bias + col);
                v.x += bb.x; v.y += bb.y; v.z += bb.z; v.w += bb.w;
                if (EPI == 1) {
                    v.x = tanhf(v.x); v.y = tanhf(v.y); v.z = tanhf(v.z); v.w = tanhf(v.w);
                } else {
                    v.x = fmaxf(v.x, 0.f); v.y = fmaxf(v.y, 0.f);
                    v.z = fmaxf(v.z, 0.f); v.w = fmaxf(v.w, 0.f);
                }
            }
            *(float4*)(C + (size_t)row * N + col) = v;
        }
    }
}

// ---------------- assignment: softmax(U @ Wc2 + bc2), U in half -------------
__global__ void k_assign(const __half* __restrict__ U, const float* __restrict__ Wc2,
                         const float* __restrict__ bc2) {
    __shared__ float w[HID * 2];
    int tid = threadIdx.x;
    for (int i = tid; i < HID * 2; i += 128) w[i] = Wc2[i];
    __syncthreads();
    int warp = tid >> 5, lane = tid & 31;
    int n = blockIdx.x * 4 + warp;
    const __half2* u2 = (const __half2*)(U + (size_t)n * HID);
    float s0 = 0.f, s1 = 0.f;
    for (int k = lane; k < HID / 2; k += 32) {
        float2 uv = __half22float2(u2[k]);
        s0 = fmaf(uv.x, w[4 * k], s0);
        s1 = fmaf(uv.x, w[4 * k + 1], s1);
        s0 = fmaf(uv.y, w[4 * k + 2], s0);
        s1 = fmaf(uv.y, w[4 * k + 3], s1);
    }
#pragma unroll
    for (int o = 16; o > 0; o >>= 1) {
        s0 += __shfl_xor_sync(0xffffffff, s0, o);
        s1 += __shfl_xor_sync(0xffffffff, s1, o);
    }
    if (lane == 0) {
        float z0 = s0 + bc2[0], z1 = s1 + bc2[1];
        float m = fmaxf(z0, z1);
        float e0 = expf(z0 - m), e1 = expf(z1 - m);
        float inv = 1.f / (e0 + e1);
        d_assign[n * 2] = e0 * inv;
        d_assign[n * 2 + 1] = e1 * inv;
    }
}

// ---------------- pos + global h column sums (reads half h) -----------------
__global__ void k_pos(const __half* __restrict__ H) {
    __shared__ float a0[NPG];
    int g = blockIdx.x, c = threadIdx.x;
    if (c < NPG) a0[c] = d_assign[(g * NPG + c) * 2];
    __syncthreads();
    const __half* h = H + (size_t)g * NPG * HID;
    float acc = 0.f, gs = 0.f;
    for (int n = 0; n < NPG; ++n) {
        float hv = __half2float(h[n * HID + c]);
        acc = fmaf(a0[n], hv, acc);
        gs += hv;
    }
    d_pos[g * HID + c] = acc;
    atomicAdd(&d_gvec[c], gs);
}

// ---------------- new_adj + penalty ----------------------------------------
__global__ void k_newadj(const int* __restrict__ ei) {
    __shared__ float sa[NPG * 2];
    __shared__ float red[4][4];
    int g = blockIdx.x, tid = threadIdx.x;
    if (tid < NPG * 2) sa[tid] = d_assign[g * NPG * 2 + tid];
    __syncthreads();
    float a00 = 0, a01 = 0, a10 = 0, a11 = 0;
    for (int e = tid; e < EPG; e += 128) {
        int s = ei[g * EPG + e] - g * NPG;
        int d = ei[N_EDGES + g * EPG + e] - g * NPG;
        float s0 = sa[2 * s], s1 = sa[2 * s + 1];
        float t0 = sa[2 * d], t1 = sa[2 * d + 1];
        a00 = fmaf(s0, t0, a00); a01 = fmaf(s0, t1, a01);
        a10 = fmaf(s1, t0, a10); a11 = fmaf(s1, t1, a11);
    }
#pragma unroll
    for (int o = 16; o > 0; o >>= 1) {
        a00 += __shfl_xor_sync(0xffffffff, a00, o);
        a01 += __shfl_xor_sync(0xffffffff, a01, o);
        a10 += __shfl_xor_sync(0xffffffff, a10, o);
        a11 += __shfl_xor_sync(0xffffffff, a11, o);
    }
    int warp = tid >> 5, lane = tid & 31;
    if (lane == 0) {
        red[warp][0] = a00; red[warp][1] = a01;
        red[warp][2] = a10; red[warp][3] = a11;
    }
    __syncthreads();
    if (tid < 4) {
        float v = red[0][tid] + red[1][tid] + red[2][tid] + red[3][tid];
        d_newadj[g * 4 + tid] = v;
    }
}

__global__ void k_penalty(float* __restrict__ out) {
    __shared__ float red[NG];
    int g = threadIdx.x;
    float a00 = d_newadj[g * 4], a01 = d_newadj[g * 4 + 1];
    float a10 = d_newadj[g * 4 + 2], a11 = d_newadj[g * 4 + 3];
    float r0 = fmaxf(fabsf(a00) + fabsf(a01), EPSV);
    float r1 = fmaxf(fabsf(a10) + fabsf(a11), EPSV);
    float dd0 = a00 / r0 - 1.f, dd1 = a11 / r1 - 1.f;
    red[g] = dd0 * dd0 + dd1 * dd1;
    __syncthreads();
    for (int s = 256; s > 0; s >>= 1) {
        if (g < s) red[g] += red[g + s];
        __syncthreads();
    }
    if (g == 0) out[OUT_PEN] = red[0] * (1.f / (NG * 2.f));
}

// ---------------- norm reductions ------------------------------------------
__global__ void k_sumsq_pos() {
    __shared__ float red[256];
    int tid = threadIdx.x;
    float s = 0.f;
    for (int i = blockIdx.x * 256 + tid; i < NG * HID; i += gridDim.x * 256) {
        float v = d_pos[i];
        s = fmaf(v, v, s);
    }
    red[tid] = s;
    __syncthreads();
    for (int o = 128; o > 0; o >>= 1) {
        if (tid < o) red[tid] += red[tid + o];
        __syncthreads();
    }
    if (tid == 0) atomicAdd(&d_scal[0], red[0]);
}

__global__ void k_pg() {
    __shared__ float red[HID];
    int t = threadIdx.x;
    float v = d_gvec[t] * (1.f / (float)N_NODES);
    red[t] = v * v;
    __syncthreads();
    for (int s = 256; s > 0; s >>= 1) {
        if (t < s) red[t] += red[t + s];
        __syncthreads();
    }
    if (t == 0) d_scal[1] = red[0] * (1.f / (float)HID);
}

__global__ void k_finpos(float* __restrict__ out) {
    int i = blockIdx.x * blockDim.x + threadIdx.x;
    if (i < NG * HID) {
        float ms = d_scal[0] * (1.f / (float)(NG * HID));
        float sc = (ms > 1.f) ? rsqrtf(ms) : 1.f;
        float v = d_pos[i] * sc;
        d_pos[i] = v;
        out[OUT_POS + i] = v;
    }
}

__global__ void k_fingemb(float* __restrict__ out) {
    int i = blockIdx.x * blockDim.x + threadIdx.x;
    if (i < NG * HID) {
        float ms = d_scal[1];
        float sc = (ms > 1.f) ? rsqrtf(ms) : 1.f;
        float v = d_gvec[i & (HID - 1)] * (1.f / (float)N_NODES) * sc;
        out[OUT_GEMB + i] = v;
    }
}

// ---------------- head ------------------------------------------------------
__global__ void k_head(const float* __restrict__ Z, const float* __restrict__ Wl2,
                       const float* __restrict__ bl2, float* __restrict__ out) {
    __shared__ float w[HID * 6];
    int tid = threadIdx.x;
    for (int i = tid; i < HID * 6; i += 128) w[i] = Wl2[i];
    __syncthreads();
    int warp = tid >> 5, lane = tid & 31;
    int row = blockIdx.x * 4 + warp;
    const float* z = Z + (size_t)row * HID;
    float s[6] = {0, 0, 0, 0, 0, 0};
    for (int k = lane; k < HID; k += 32) {
        float zv = z[k];
#pragma unroll
        for (int j = 0; j < 6; ++j) s[j] = fmaf(zv, w[k * 6 + j], s[j]);
    }
#pragma unroll
    for (int o = 16; o > 0; o >>= 1)
#pragma unroll
        for (int j = 0; j < 6; ++j) s[j] += __shfl_xor_sync(0xffffffff, s[j], o);
    if (lane == 0) {
        float o6[6], m = -1e30f;
#pragma unroll
        for (int j = 0; j < 6; ++j) { o6[j] = s[j] + bl2[j]; m = fmaxf(m, o6[j]); }
        float sum = 0.f;
#pragma unroll
        for (int j = 0; j < 6; ++j) sum += expf(o6[j] - m);
        float lse = m + logf(sum);
#pragma unroll
        for (int j = 0; j < 6; ++j) out[OUT_LOGP + row * 6 + j] = o6[j] - lse;
    }
}

// ---------------- launch ----------------------------------------------------
extern "C" void kernel_launch(void* const* d_in, const int* in_sizes, int n_in,
                              void* d_out, int out_size) {
    const float* x   = (const float*)d_in[0];
    const int*   ei  = (const int*)d_in[1];
    const float* W1  = (const float*)d_in[4];
    const float* b1  = (const float*)d_in[5];
    const float* W2  = (const float*)d_in[6];
    const float* b2  = (const float*)d_in[7];
    const float* W3  = (const float*)d_in[8];
    const float* b3  = (const float*)d_in[9];
    const float* Wc1 = (const float*)d_in[10];
    const float* bc1 = (const float*)d_in[11];
    const float* Wc2 = (const float*)d_in[12];
    const float* bc2 = (const float*)d_in[13];
    const float* Wl1 = (const float*)d_in[14];
    const float* bl1 = (const float*)d_in[15];
    const float* Wl2 = (const float*)d_in[16];
    const float* bl2 = (const float*)d_in[17];
    float* out = (float*)d_out;

    float *pT, *pPos;
    __half *pTh, *pHh, *pXh, *pWh;
    cudaGetSymbolAddress((void**)&pT, d_T);
    cudaGetSymbolAddress((void**)&pPos, d_pos);
    cudaGetSymbolAddress((void**)&pTh, d_Th);
    cudaGetSymbolAddress((void**)&pHh, d_Hh);
    cudaGetSymbolAddress((void**)&pXh, d_Xh);
    cudaGetSymbolAddress((void**)&pWh, d_Wh);

    cudaFuncSetAttribute(k_aggh, cudaFuncAttributeMaxDynamicSharedMemorySize, AGGH_SMEM);
    cudaFuncSetAttribute(hgemm<FIN, 0>, cudaFuncAttributeMaxDynamicSharedMemorySize, HG_SMEM);
    cudaFuncSetAttribute(hgemm<HID, 0>, cudaFuncAttributeMaxDynamicSharedMemorySize, HG_SMEM);
    cudaFuncSetAttribute(hgemm<HID, 1>, cudaFuncAttributeMaxDynamicSharedMemorySize, HG_SMEM);

    __half* Wh0 = pWh;
    __half* Wh1 = pWh + HID * HID;
    __half* Wh2 = pWh + 2 * HID * HID;
    __half* Wh3 = pWh + 3 * HID * HID;

    // fused graph structure build + misc zero
    k_zero_misc<<<1, 512>>>();
    k_build<<<NG, 256>>>(ei);

    // weight transposes (fp32 -> half, transposed)
    dim3 tb(32, 8);
    k_transpose_h<<<dim3(HID / 32, FIN / 32), tb>>>(W1, Wh0, FIN, HID);
    k_transpose_h<<<dim3(HID / 32, HID / 32), tb>>>(W2, Wh1, HID, HID);
    k_transpose_h<<<dim3(HID / 32, HID / 32), tb>>>(W3, Wh2, HID, HID);
    k_transpose_h<<<dim3(HID / 32, HID / 32), tb>>>(Wc1, Wh3, HID, HID);
    k_x2h<<<(N_NODES * FIN / 2 + 255) / 256, 256>>>((const float2*)x, (__half2*)pXh);

    dim3 gBig(HID / 128, N_NODES / 128);
    dim3 gAgg(NG, 4);

    // 3 GCN layers: T = H@W (fp16 tensor) ; H = A_hat @ T + b (fp16 tensor)
    hgemm<FIN, 0><<<gBig, 256, HG_SMEM>>>(pXh, Wh0, nullptr, pTh);
    k_aggh<<<gAgg, 256, AGGH_SMEM>>>(pTh, b1, pHh);
    hgemm<HID, 0><<<gBig, 256, HG_SMEM>>>(pHh, Wh1, nullptr, pTh);
    k_aggh<<<gAgg, 256, AGGH_SMEM>>>(pTh, b2, pHh);
    hgemm<HID, 0><<<gBig, 256, HG_SMEM>>>(pHh, Wh2, nullptr, pTh);
    k_aggh<<<gAgg, 256, AGGH_SMEM>>>(pTh, b3, pHh);

    // assignment = softmax(tanh(h@Wc1+bc1)@Wc2+bc2)
    hgemm<HID, 1><<<gBig, 256, HG_SMEM>>>(pHh, Wh3, bc1, pTh);
    k_assign<<<N_NODES / 4, 128>>>(pTh, Wc2, bc2);

    // pooling / penalty
    k_pos<<<NG, HID>>>(pHh);
    k_newadj<<<NG, 128>>>(ei);
    k_penalty<<<1, NG>>>(out);

    // normalizations
    k_sumsq_pos<<<256, 256>>>();
    k_pg<<<1, HID>>>();
    k_finpos<<<1024, 256>>>(out);
    k_fingemb<<<1024, 256>>>(out);

    // head MLP on normalized pos (fp32)
    dim3 gHead(HID / 128, NG / 128);
    sgemm<2><<<gHead, 256>>>(pPos, Wl1, bl1, pT, NG, HID, HID);
    k_head<<<NG / 4, 128>>>(pT, Wl2, bl2, out);
}

// round 7
// speedup vs baseline: 3.8037x; 1.0591x over previous
#include <cuda_runtime.h>
#include <cuda_fp16.h>
#include <math.h>
#include <cstdint>

#define N_NODES 51200
#define N_EDGES 819200
#define NG 512
#define NPG 100
#define EPG 1600
#define HID 512
#define FIN 128
#define EPSV 1e-5f

#define OUT_LOGP 0
#define OUT_POS 3072
#define OUT_GEMB 265216
#define OUT_PEN 527360

// ---------------- scratch (static device allocations; no cudaMalloc) --------
__device__ __half d_Ah[NG * 128 * 120];        // padded half adjacency [g][m:128][k:120]
__device__ __half d_Th[N_NODES * HID];         // GEMM output (half)
__device__ __half d_Hh[N_NODES * HID];         // agg output (half)
__device__ __half d_Xh[N_NODES * FIN];         // x in half
__device__ __half d_Wh[4][HID * HID];          // transposed half weights [N][K]
__device__ float d_T[N_NODES * HID];           // fp32 scratch (head path)
__device__ float d_araw[N_NODES * 2];          // raw assignment logits (atomic acc)
__device__ float d_assign[N_NODES * 2];
__device__ float d_pos[NG * HID];
__device__ float d_gvec[HID];
__device__ float d_newadj[NG * 4];
__device__ float d_scal[4];

// ---------------- ptx helpers ----------------------------------------------
__device__ __forceinline__ uint32_t s2u(const void* p) {
    uint32_t a;
    asm("{ .reg .u64 t; cvta.to.shared.u64 t, %1; cvt.u32.u64 %0, t; }"
        : "=r"(a) : "l"(p));
    return a;
}
__device__ __forceinline__ void cp16(uint32_t s, const void* g) {
    asm volatile("cp.async.cg.shared.global [%0], [%1], 16;" :: "r"(s), "l"(g));
}
__device__ __forceinline__ void mma_f16(float* c, const uint32_t* a, const uint32_t* b) {
    asm volatile(
        "mma.sync.aligned.m16n8k16.row.col.f32.f16.f16.f32 "
        "{%0,%1,%2,%3}, {%4,%5,%6,%7}, {%8,%9}, {%0,%1,%2,%3};"
        : "+f"(c[0]), "+f"(c[1]), "+f"(c[2]), "+f"(c[3])
        : "r"(a[0]), "r"(a[1]), "r"(a[2]), "r"(a[3]), "r"(b[0]), "r"(b[1]));
}
__device__ __forceinline__ void ldm4(uint32_t* r, uint32_t addr) {
    asm volatile("ldmatrix.sync.aligned.m8n8.x4.shared.b16 {%0,%1,%2,%3}, [%4];"
                 : "=r"(r[0]), "=r"(r[1]), "=r"(r[2]), "=r"(r[3]) : "r"(addr));
}

// ---------------- fused per-graph structure build ---------------------------
__global__ void __launch_bounds__(256) k_build(const int* __restrict__ ei) {
    __shared__ float Adj[NPG * NPG];
    __shared__ float deg[NPG];
    __shared__ float dis[NPG];
    int g = blockIdx.x, tid = threadIdx.x;
    for (int i = tid; i < NPG * NPG; i += 256) Adj[i] = 0.f;
    if (tid < NPG) deg[tid] = 0.f;
    __syncthreads();
    const int* src = ei + g * EPG;
    const int* dst = ei + N_EDGES + g * EPG;
    int base = g * NPG;
    for (int e = tid; e < EPG; e += 256) atomicAdd(&deg[dst[e] - base], 1.f);
    __syncthreads();
    if (tid < NPG) dis[tid] = rsqrtf(deg[tid] + 1.f);
    __syncthreads();
    for (int e = tid; e < EPG; e += 256) {
        int s = src[e] - base, d = dst[e] - base;
        atomicAdd(&Adj[d * NPG + s], dis[s] * dis[d]);
    }
    __syncthreads();
    if (tid < NPG) Adj[tid * NPG + tid] += dis[tid] * dis[tid];
    __syncthreads();
    __half2* out = (__half2*)(d_Ah + (size_t)g * 128 * 120);
    for (int i = tid; i < 128 * 60; i += 256) {
        int r = i / 60, k = (i % 60) * 2;
        float v0 = (r < NPG && k < NPG) ? Adj[r * NPG + k] : 0.f;
        float v1 = (r < NPG && k + 1 < NPG) ? Adj[r * NPG + k + 1] : 0.f;
        out[i] = __floats2half2_rn(v0, v1);
    }
}

__global__ void k_zero_misc() {   // grid 100 x 1024
    int i = blockIdx.x * 1024 + threadIdx.x;
    if (i < N_NODES * 2) d_araw[i] = 0.f;
    if (i < HID) d_gvec[i] = 0.f;
    if (i < 4) d_scal[i] = 0.f;
}

// ---------------- weight transpose to half: Wt[n][k] = h(W[k][n]) -----------
__global__ void k_transpose_h(const float* __restrict__ W, __half* __restrict__ Wt,
                              int K, int N) {
    __shared__ float tile[32][33];
    int k0 = blockIdx.y * 32, n0 = blockIdx.x * 32;
    int tx = threadIdx.x, ty = threadIdx.y;
    for (int j = ty; j < 32; j += 8) tile[j][tx] = W[(size_t)(k0 + j) * N + n0 + tx];
    __syncthreads();
    for (int j = ty; j < 32; j += 8)
        Wt[(size_t)(n0 + j) * K + k0 + tx] = __float2half_rn(tile[tx][j]);
}

__global__ void k_x2h(const float2* __restrict__ x, __half2* __restrict__ o) {
    int i = blockIdx.x * blockDim.x + threadIdx.x;
    if (i < N_NODES * FIN / 2) o[i] = __float22half2_rn(x[i]);
}

// ---------------- fp16 mma GEMM: C[M,512] = A[M,K] @ Wt[512,K]^T ------------
// 128x128 CTA tile, 8 warps (64x32 warp tile), BK=32, 3-stage cp.async,
// ldmatrix fragment loads.
// EPI: 0 = plain half out, 2 = fused assignment head (tanh + Wc2 dot + atomic)
#define HG_SMEM (3 * 2 * 128 * 40 * 2)
template <int K, int EPI>
__global__ void __launch_bounds__(256) hgemm(const __half* __restrict__ A,
                                             const __half* __restrict__ Bt,
                                             const float* __restrict__ bias,
                                             __half* __restrict__ C,
                                             const float* __restrict__ wc2) {
    constexpr int NT = K / 32;
    extern __shared__ __half hsh[];
    __half* As = hsh;
    __half* Bs = hsh + 3 * 128 * 40;
    int tid = threadIdx.x;
    int wid = tid >> 5, lane = tid & 31;
    int g = lane >> 2, q = lane & 3;
    int wm = wid >> 2, wn = wid & 3;
    int m0 = blockIdx.y * 128, n0 = blockIdx.x * 128;

    int lr = tid >> 1, lc = tid & 1;
    const __half* Ag = A + (size_t)(m0 + lr) * K + lc * 16;
    const __half* Bg = Bt + (size_t)(n0 + lr) * K + lc * 16;
    uint32_t sa = s2u(&As[lr * 40 + lc * 16]);
    uint32_t sb = s2u(&Bs[lr * 40 + lc * 16]);
    const uint32_t STB = 128 * 40 * 2;

    auto load_stage = [&](int kt, int st) {
        uint32_t o = st * STB;
        cp16(sa + o, Ag + kt * 32);
        cp16(sa + o + 16, Ag + kt * 32 + 8);
        cp16(sb + o, Bg + kt * 32);
        cp16(sb + o + 16, Bg + kt * 32 + 8);
        asm volatile("cp.async.commit_group;" ::: "memory");
    };

    // ldmatrix per-lane geometry
    uint32_t AsU = s2u(As), BsU = s2u(Bs);
    int laneA = (wm * 64 + (lane & 15)) * 40 + ((lane >> 4) & 1) * 8;
    int laneB = (wn * 32 + ((lane >> 4) & 1) * 8 + (lane & 7)) * 40
                + ((lane >> 3) & 1) * 8;

    float acc[4][4][4];
#pragma unroll
    for (int i = 0; i < 4; ++i)
#pragma unroll
        for (int j = 0; j < 4; ++j)
#pragma unroll
            for (int t = 0; t < 4; ++t) acc[i][j][t] = 0.f;

    load_stage(0, 0);
    if (NT > 1) load_stage(1, 1);

#pragma unroll 1
    for (int kt = 0; kt < NT; ++kt) {
        if (kt + 2 < NT) {
            load_stage(kt + 2, (kt + 2) % 3);
            asm volatile("cp.async.wait_group 2;" ::: "memory");
        } else if (kt + 1 < NT) {
            asm volatile("cp.async.wait_group 1;" ::: "memory");
        } else {
            asm volatile("cp.async.wait_group 0;" ::: "memory");
        }
        __syncthreads();

        uint32_t so = (kt % 3) * STB;
#pragma unroll
        for (int ks = 0; ks < 2; ++ks) {
            uint32_t ko = ks * 32;   // 16 halves
            uint32_t af[4][4], bf[4][2];
#pragma unroll
            for (int mi = 0; mi < 4; ++mi)
                ldm4(af[mi], AsU + so + (laneA + mi * 16 * 40) * 2 + ko);
#pragma unroll
            for (int p = 0; p < 2; ++p)
                ldm4(&bf[2 * p][0], BsU + so + (laneB + p * 16 * 40) * 2 + ko);
#pragma unroll
            for (int mi = 0; mi < 4; ++mi)
#pragma unroll
                for (int ni = 0; ni < 4; ++ni)
                    mma_f16(acc[mi][ni], af[mi], bf[ni]);
        }
        __syncthreads();
    }

    if (EPI == 0) {
#pragma unroll
        for (int mi = 0; mi < 4; ++mi) {
            int row0 = m0 + wm * 64 + mi * 16 + g;
#pragma unroll
            for (int ni = 0; ni < 4; ++ni) {
                int col = n0 + wn * 32 + ni * 8 + 2 * q;
                *(half2*)(C + (size_t)row0 * HID + col) =
                    __floats2half2_rn(acc[mi][ni][0], acc[mi][ni][1]);
                *(half2*)(C + (size_t)(row0 + 8) * HID + col) =
                    __floats2half2_rn(acc[mi][ni][2], acc[mi][ni][3]);
            }
        }
    } else {
        // fused assignment head: s = sum_col tanh(acc+bc1[col]) * Wc2[col][:]
        float wc[4][4];
#pragma unroll
        for (int ni = 0; ni < 4; ++ni) {
            int col = n0 + wn * 32 + ni * 8 + 2 * q;
            float4 w4 = *(const float4*)(wc2 + col * 2);
            wc[ni][0] = w4.x; wc[ni][1] = w4.y; wc[ni][2] = w4.z; wc[ni][3] = w4.w;
        }
        float s[4][2][2];
#pragma unroll
        for (int mi = 0; mi < 4; ++mi)
#pragma unroll
            for (int r = 0; r < 2; ++r) { s[mi][r][0] = 0.f; s[mi][r][1] = 0.f; }
#pragma unroll
        for (int mi = 0; mi < 4; ++mi)
#pragma unroll
            for (int ni = 0; ni < 4; ++ni) {
                int col = n0 + wn * 32 + ni * 8 + 2 * q;
                float2 bb = *(const float2*)(bias + col);
                float v0 = tanhf(acc[mi][ni][0] + bb.x);
                float v1 = tanhf(acc[mi][ni][1] + bb.y);
                float v2 = tanhf(acc[mi][ni][2] + bb.x);
                float v3 = tanhf(acc[mi][ni][3] + bb.y);
                s[mi][0][0] += v0 * wc[ni][0] + v1 * wc[ni][2];
                s[mi][0][1] += v0 * wc[ni][1] + v1 * wc[ni][3];
                s[mi][1][0] += v2 * wc[ni][0] + v3 * wc[ni][2];
                s[mi][1][1] += v2 * wc[ni][1] + v3 * wc[ni][3];
            }
#pragma unroll
        for (int mi = 0; mi < 4; ++mi)
#pragma unroll
            for (int r = 0; r < 2; ++r)
#pragma unroll
                for (int c = 0; c < 2; ++c) {
                    float v = s[mi][r][c];
                    v += __shfl_xor_sync(0xffffffff, v, 1);
                    v += __shfl_xor_sync(0xffffffff, v, 2);
                    s[mi][r][c] = v;
                }
        if (q == 0) {
#pragma unroll
            for (int mi = 0; mi < 4; ++mi)
#pragma unroll
                for (int r = 0; r < 2; ++r) {
                    int row = m0 + wm * 64 + mi * 16 + g + r * 8;
                    atomicAdd(&d_araw[row * 2], s[mi][r][0]);
                    atomicAdd(&d_araw[row * 2 + 1], s[mi][r][1]);
                }
        }
    }
}

// ---------------- tensor-core agg: H = A_g @ T_g + b ------------------------
#define AGGH_SMEM (2 * 128 * 120 * 2)
__global__ void __launch_bounds__(256) k_aggh(const __half* __restrict__ T,
                                              const float* __restrict__ bias,
                                              __half* __restrict__ Hh) {
    extern __shared__ __half aggsh[];
    __half* Ash = aggsh;
    __half* Ts = aggsh + 128 * 120;
    int gph = blockIdx.x;
    int cb = blockIdx.y * 128;
    int tid = threadIdx.x;
    int wid = tid >> 5, lane = tid & 31;
    int g = lane >> 2, q = lane & 3;
    int wm = wid >> 1, wn = wid & 1;

    const uint4* Asrc = (const uint4*)(d_Ah + (size_t)gph * 128 * 120);
    uint4* Adst = (uint4*)Ash;
    for (int i = tid; i < 128 * 120 / 8; i += 256) Adst[i] = Asrc[i];

    const __half* Tg = T + (size_t)gph * NPG * HID + cb;
    for (int i = tid; i < NPG * 128; i += 256) {
        int k = i >> 7, n = i & 127;
        Ts[n * 120 + k] = Tg[(size_t)k * HID + n];
    }
    for (int i = tid; i < 128 * 12; i += 256) {
        int n = i / 12, k = NPG + i % 12;
        Ts[n * 120 + k] = __float2half(0.f);
    }
    __syncthreads();

    uint32_t AshU = s2u(Ash), TsU = s2u(Ts);
    int laneA = (wm * 32 + (lane & 15)) * 120 + ((lane >> 4) & 1) * 8;
    int laneB = (wn * 64 + ((lane >> 4) & 1) * 8 + (lane & 7)) * 120
                + ((lane >> 3) & 1) * 8;

    float acc[2][8][4];
#pragma unroll
    for (int i = 0; i < 2; ++i)
#pragma unroll
        for (int j = 0; j < 8; ++j)
#pragma unroll
            for (int t = 0; t < 4; ++t) acc[i][j][t] = 0.f;

#pragma unroll
    for (int k0 = 0; k0 < 112; k0 += 16) {
        uint32_t af[2][4], bf[8][2];
#pragma unroll
        for (int mi = 0; mi < 2; ++mi)
            ldm4(af[mi], AshU + (laneA + mi * 16 * 120 + k0) * 2);
#pragma unroll
        for (int p = 0; p < 4; ++p)
            ldm4(&bf[2 * p][0], TsU + (laneB + p * 16 * 120 + k0) * 2);
#pragma unroll
        for (int mi = 0; mi < 2; ++mi)
#pragma unroll
            for (int ni = 0; ni < 8; ++ni)
                mma_f16(acc[mi][ni], af[mi], bf[ni]);
    }

#pragma unroll
    for (int mi = 0; mi < 2; ++mi) {
        int rl = wm * 32 + mi * 16 + g;
#pragma unroll
        for (int ni = 0; ni < 8; ++ni) {
            int col = cb + wn * 64 + ni * 8 + 2 * q;
            float2 bb = *(const float2*)(bias + col);
            if (rl < NPG) {
                size_t off = ((size_t)gph * NPG + rl) * HID + col;
                *(half2*)(Hh + off) =
                    __floats2half2_rn(acc[mi][ni][0] + bb.x, acc[mi][ni][1] + bb.y);
            }
            if (rl + 8 < NPG) {
                size_t off = ((size_t)gph * NPG + rl + 8) * HID + col;
                *(half2*)(Hh + off) =
                    __floats2half2_rn(acc[mi][ni][2] + bb.x, acc[mi][ni][3] + bb.y);
            }
        }
    }
}

// ---------------- fp32 tiled SGEMM (head only) ------------------------------
template <int EPI>
__global__ void sgemm(const float* __restrict__ A, const float* __restrict__ B,
                      const float* __restrict__ bias, float* __restrict__ C,
                      int M, int N, int K) {
    __shared__ float As[8][128];
    __shared__ float Bs[8][128];
    int tid = threadIdx.x;
    int m0 = blockIdx.y * 128;
    int n0 = blockIdx.x * 128;
    int arow = tid >> 1;
    int acol = (tid & 1) * 4;
    int brow = tid >> 5;
    int bcol = (tid & 31) * 4;
    int ty = tid >> 4;
    int tx = tid & 15;
    float acc[8][8] = {};

    for (int k0 = 0; k0 < K; k0 += 8) {
        float4 av = *(const float4*)(A + (size_t)(m0 + arow) * K + k0 + acol);
        As[acol + 0][arow] = av.x;
        As[acol + 1][arow] = av.y;
        As[acol + 2][arow] = av.z;
        As[acol + 3][arow] = av.w;
        *(float4*)(&Bs[brow][bcol]) =
            *(const float4*)(B + (size_t)(k0 + brow) * N + n0 + bcol);
        __syncthreads();
#pragma unroll
        for (int k = 0; k < 8; ++k) {
            float a[8], b[8];
            *(float4*)(a) = *(float4*)(&As[k][ty * 8]);
            *(float4*)(a + 4) = *(float4*)(&As[k][ty * 8 + 4]);
            *(float4*)(b) = *(float4*)(&Bs[k][tx * 8]);
            *(float4*)(b + 4) = *(float4*)(&Bs[k][tx * 8 + 4]);
#pragma unroll
            for (int i = 0; i < 8; ++i)
#pragma unroll
                for (int j = 0; j < 8; ++j) acc[i][j] = fmaf(a[i], b[j], acc[i][j]);
        }
        __syncthreads();
    }
#pragma unroll
    for (int i = 0; i < 8; ++i) {
        int row = m0 + ty * 8 + i;
#pragma unroll
        for (int j = 0; j < 8; j += 4) {
            int col = n0 + tx * 8 + j;
            float4 v = make_float4(acc[i][j], acc[i][j + 1], acc[i][j + 2], acc[i][j + 3]);
            if (EPI != 0) {
                float4 bb = *(const float4*)(bias + col);
                v.x += bb.x; v.y += bb.y; v.z += bb.z; v.w += bb.w;
                if (EPI == 1) {
                    v.x = tanhf(v.x); v.y = tanhf(v.y); v.z = tanhf(v.z); v.w = tanhf(v.w);
                } else {
                    v.x = fmaxf(v.x, 0.f); v.y = fmaxf(v.y, 0.f);
                    v.z = fmaxf(v.z, 0.f); v.w = fmaxf(v.w, 0.f);
                }
            }
            *(float4*)(C + (size_t)row * N + col) = v;
        }
    }
}

// ---------------- assignment softmax from raw logits ------------------------
__global__ void k_assign2(const float* __restrict__ bc2) {
    int n = blockIdx.x * blockDim.x + threadIdx.x;
    if (n < N_NODES) {
        float z0 = d_araw[2 * n] + bc2[0], z1 = d_araw[2 * n + 1] + bc2[1];
        float m = fmaxf(z0, z1);
        float e0 = expf(z0 - m), e1 = expf(z1 - m);
        float inv = 1.f / (e0 + e1);
        d_assign[2 * n] = e0 * inv;
        d_assign[2 * n + 1] = e1 * inv;
    }
}

// ---------------- pos + global h column sums (reads half h) -----------------
__global__ void k_pos(const __half* __restrict__ H) {
    __shared__ float a0[NPG];
    int g = blockIdx.x, c = threadIdx.x;
    if (c < NPG) a0[c] = d_assign[(g * NPG + c) * 2];
    __syncthreads();
    const __half* h = H + (size_t)g * NPG * HID;
    float acc = 0.f, gs = 0.f;
    for (int n = 0; n < NPG; ++n) {
        float hv = __half2float(h[n * HID + c]);
        acc = fmaf(a0[n], hv, acc);
        gs += hv;
    }
    d_pos[g * HID + c] = acc;
    atomicAdd(&d_gvec[c], gs);
}

// ---------------- new_adj + penalty ----------------------------------------
__global__ void k_newadj(const int* __restrict__ ei) {
    __shared__ float sa[NPG * 2];
    __shared__ float red[4][4];
    int g = blockIdx.x, tid = threadIdx.x;
    if (tid < NPG * 2) sa[tid] = d_assign[g * NPG * 2 + tid];
    __syncthreads();
    float a00 = 0, a01 = 0, a10 = 0, a11 = 0;
    for (int e = tid; e < EPG; e += 128) {
        int s = ei[g * EPG + e] - g * NPG;
        int d = ei[N_EDGES + g * EPG + e] - g * NPG;
        float s0 = sa[2 * s], s1 = sa[2 * s + 1];
        float t0 = sa[2 * d], t1 = sa[2 * d + 1];
        a00 = fmaf(s0, t0, a00); a01 = fmaf(s0, t1, a01);
        a10 = fmaf(s1, t0, a10); a11 = fmaf(s1, t1, a11);
    }
#pragma unroll
    for (int o = 16; o > 0; o >>= 1) {
        a00 += __shfl_xor_sync(0xffffffff, a00, o);
        a01 += __shfl_xor_sync(0xffffffff, a01, o);
        a10 += __shfl_xor_sync(0xffffffff, a10, o);
        a11 += __shfl_xor_sync(0xffffffff, a11, o);
    }
    int warp = tid >> 5, lane = tid & 31;
    if (lane == 0) {
        red[warp][0] = a00; red[warp][1] = a01;
        red[warp][2] = a10; red[warp][3] = a11;
    }
    __syncthreads();
    if (tid < 4) {
        float v = red[0][tid] + red[1][tid] + red[2][tid] + red[3][tid];
        d_newadj[g * 4 + tid] = v;
    }
}

__global__ void k_penalty(float* __restrict__ out) {
    __shared__ float red[NG];
    int g = threadIdx.x;
    float a00 = d_newadj[g * 4], a01 = d_newadj[g * 4 + 1];
    float a10 = d_newadj[g * 4 + 2], a11 = d_newadj[g * 4 + 3];
    float r0 = fmaxf(fabsf(a00) + fabsf(a01), EPSV);
    float r1 = fmaxf(fabsf(a10) + fabsf(a11), EPSV);
    float dd0 = a00 / r0 - 1.f, dd1 = a11 / r1 - 1.f;
    red[g] = dd0 * dd0 + dd1 * dd1;
    __syncthreads();
    for (int s = 256; s > 0; s >>= 1) {
        if (g < s) red[g] += red[g + s];
        __syncthreads();
    }
    if (g == 0) out[OUT_PEN] = red[0] * (1.f / (NG * 2.f));
}

// ---------------- norm reductions ------------------------------------------
__global__ void k_sumsq_pos() {
    __shared__ float red[256];
    int tid = threadIdx.x;
    float s = 0.f;
    for (int i = blockIdx.x * 256 + tid; i < NG * HID; i += gridDim.x * 256) {
        float v = d_pos[i];
        s = fmaf(v, v, s);
    }
    red[tid] = s;
    __syncthreads();
    for (int o = 128; o > 0; o >>= 1) {
        if (tid < o) red[tid] += red[tid + o];
        __syncthreads();
    }
    if (tid == 0) atomicAdd(&d_scal[0], red[0]);
}

__global__ void k_pg() {
    __shared__ float red[HID];
    int t = threadIdx.x;
    float v = d_gvec[t] * (1.f / (float)N_NODES);
    red[t] = v * v;
    __syncthreads();
    for (int s = 256; s > 0; s >>= 1) {
        if (t < s) red[t] += red[t + s];
        __syncthreads();
    }
    if (t == 0) d_scal[1] = red[0] * (1.f / (float)HID);
}

__global__ void k_finpos(float* __restrict__ out) {
    int i = blockIdx.x * blockDim.x + threadIdx.x;
    if (i < NG * HID) {
        float ms = d_scal[0] * (1.f / (float)(NG * HID));
        float sc = (ms > 1.f) ? rsqrtf(ms) : 1.f;
        float v = d_pos[i] * sc;
        d_pos[i] = v;
        out[OUT_POS + i] = v;
    }
}

__global__ void k_fingemb(float* __restrict__ out) {
    int i = blockIdx.x * blockDim.x + threadIdx.x;
    if (i < NG * HID) {
        float ms = d_scal[1];
        float sc = (ms > 1.f) ? rsqrtf(ms) : 1.f;
        float v = d_gvec[i & (HID - 1)] * (1.f / (float)N_NODES) * sc;
        out[OUT_GEMB + i] = v;
    }
}

// ---------------- head ------------------------------------------------------
__global__ void k_head(const float* __restrict__ Z, const float* __restrict__ Wl2,
                       const float* __restrict__ bl2, float* __restrict__ out) {
    __shared__ float w[HID * 6];
    int tid = threadIdx.x;
    for (int i = tid; i < HID * 6; i += 128) w[i] = Wl2[i];
    __syncthreads();
    int warp = tid >> 5, lane = tid & 31;
    int row = blockIdx.x * 4 + warp;
    const float* z = Z + (size_t)row * HID;
    float s[6] = {0, 0, 0, 0, 0, 0};
    for (int k = lane; k < HID; k += 32) {
        float zv = z[k];
#pragma unroll
        for (int j = 0; j < 6; ++j) s[j] = fmaf(zv, w[k * 6 + j], s[j]);
    }
#pragma unroll
    for (int o = 16; o > 0; o >>= 1)
#pragma unroll
        for (int j = 0; j < 6; ++j) s[j] += __shfl_xor_sync(0xffffffff, s[j], o);
    if (lane == 0) {
        float o6[6], m = -1e30f;
#pragma unroll
        for (int j = 0; j < 6; ++j) { o6[j] = s[j] + bl2[j]; m = fmaxf(m, o6[j]); }
        float sum = 0.f;
#pragma unroll
        for (int j = 0; j < 6; ++j) sum += expf(o6[j] - m);
        float lse = m + logf(sum);
#pragma unroll
        for (int j = 0; j < 6; ++j) out[OUT_LOGP + row * 6 + j] = o6[j] - lse;
    }
}

// ---------------- launch ----------------------------------------------------
extern "C" void kernel_launch(void* const* d_in, const int* in_sizes, int n_in,
                              void* d_out, int out_size) {
    const float* x   = (const float*)d_in[0];
    const int*   ei  = (const int*)d_in[1];
    const float* W1  = (const float*)d_in[4];
    const float* b1  = (const float*)d_in[5];
    const float* W2  = (const float*)d_in[6];
    const float* b2  = (const float*)d_in[7];
    const float* W3  = (const float*)d_in[8];
    const float* b3  = (const float*)d_in[9];
    const float* Wc1 = (const float*)d_in[10];
    const float* bc1 = (const float*)d_in[11];
    const float* Wc2 = (const float*)d_in[12];
    const float* bc2 = (const float*)d_in[13];
    const float* Wl1 = (const float*)d_in[14];
    const float* bl1 = (const float*)d_in[15];
    const float* Wl2 = (const float*)d_in[16];
    const float* bl2 = (const float*)d_in[17];
    float* out = (float*)d_out;

    float *pT, *pPos;
    __half *pTh, *pHh, *pXh, *pWh;
    cudaGetSymbolAddress((void**)&pT, d_T);
    cudaGetSymbolAddress((void**)&pPos, d_pos);
    cudaGetSymbolAddress((void**)&pTh, d_Th);
    cudaGetSymbolAddress((void**)&pHh, d_Hh);
    cudaGetSymbolAddress((void**)&pXh, d_Xh);
    cudaGetSymbolAddress((void**)&pWh, d_Wh);

    cudaFuncSetAttribute(k_aggh, cudaFuncAttributeMaxDynamicSharedMemorySize, AGGH_SMEM);
    cudaFuncSetAttribute(hgemm<FIN, 0>, cudaFuncAttributeMaxDynamicSharedMemorySize, HG_SMEM);
    cudaFuncSetAttribute(hgemm<HID, 0>, cudaFuncAttributeMaxDynamicSharedMemorySize, HG_SMEM);
    cudaFuncSetAttribute(hgemm<HID, 2>, cudaFuncAttributeMaxDynamicSharedMemorySize, HG_SMEM);

    __half* Wh0 = pWh;
    __half* Wh1 = pWh + HID * HID;
    __half* Wh2 = pWh + 2 * HID * HID;
    __half* Wh3 = pWh + 3 * HID * HID;

    // fused graph structure build + misc zero
    k_zero_misc<<<100, 1024>>>();
    k_build<<<NG, 256>>>(ei);

    // weight transposes (fp32 -> half, transposed)
    dim3 tb(32, 8);
    k_transpose_h<<<dim3(HID / 32, FIN / 32), tb>>>(W1, Wh0, FIN, HID);
    k_transpose_h<<<dim3(HID / 32, HID / 32), tb>>>(W2, Wh1, HID, HID);
    k_transpose_h<<<dim3(HID / 32, HID / 32), tb>>>(W3, Wh2, HID, HID);
    k_transpose_h<<<dim3(HID / 32, HID / 32), tb>>>(Wc1, Wh3, HID, HID);
    k_x2h<<<(N_NODES * FIN / 2 + 255) / 256, 256>>>((const float2*)x, (__half2*)pXh);

    dim3 gBig(HID / 128, N_NODES / 128);
    dim3 gAgg(NG, 4);

    // 3 GCN layers: T = H@W (fp16 tensor) ; H = A_hat @ T + b (fp16 tensor)
    hgemm<FIN, 0><<<gBig, 256, HG_SMEM>>>(pXh, Wh0, nullptr, pTh, nullptr);
    k_aggh<<<gAgg, 256, AGGH_SMEM>>>(pTh, b1, pHh);
    hgemm<HID, 0><<<gBig, 256, HG_SMEM>>>(pHh, Wh1, nullptr, pTh, nullptr);
    k_aggh<<<gAgg, 256, AGGH_SMEM>>>(pTh, b2, pHh);
    hgemm<HID, 0><<<gBig, 256, HG_SMEM>>>(pHh, Wh2, nullptr, pTh, nullptr);
    k_aggh<<<gAgg, 256, AGGH_SMEM>>>(pTh, b3, pHh);

    // assignment fused into 4th GEMM epilogue, then softmax
    hgemm<HID, 2><<<gBig, 256, HG_SMEM>>>(pHh, Wh3, bc1, pTh, Wc2);
    k_assign2<<<(N_NODES + 255) / 256, 256>>>(bc2);

    // pooling / penalty
    k_pos<<<NG, HID>>>(pHh);
    k_newadj<<<NG, 128>>>(ei);
    k_penalty<<<1, NG>>>(out);

    // normalizations
    k_sumsq_pos<<<256, 256>>>();
    k_pg<<<1, HID>>>();
    k_finpos<<<1024, 256>>>(out);
    k_fingemb<<<1024, 256>>>(out);

    // head MLP on normalized pos (fp32)
    dim3 gHead(HID / 128, NG / 128);
    sgemm<2><<<gHead, 256>>>(pPos, Wl1, bl1, pT, NG, HID, HID);
    k_head<<<NG / 4, 128>>>(pT, Wl2, bl2, out);
}

// round 10
// speedup vs baseline: 4.0162x; 1.0559x over previous
#include <cuda_runtime.h>
#include <cuda_fp16.h>
#include <math.h>
#include <cstdint>

#define N_NODES 51200
#define N_EDGES 819200
#define NG 512
#define NPG 100
#define EPG 1600
#define HID 512
#define FIN 128
#define EPSV 1e-5f

#define OUT_LOGP 0
#define OUT_POS 3072
#define OUT_GEMB 265216
#define OUT_PEN 527360

// ---------------- scratch (static device allocations; no cudaMalloc) --------
__device__ __half d_Ah[NG * 128 * 120];        // padded half adjacency [g][m:128][k:120]
__device__ __half d_Th[N_NODES * HID];         // GEMM output (half)
__device__ __half d_Hh[N_NODES * HID];         // agg output (half)
__device__ __half d_Xh[N_NODES * FIN];         // x in half
__device__ __half d_Wh[4][HID * HID];          // transposed half weights [N][K]
__device__ float d_T[N_NODES * HID];           // fp32 scratch (head path)
__device__ float d_araw[N_NODES * 2];          // raw assignment logits (atomic acc)
__device__ float d_assign[N_NODES * 2];
__device__ float d_pos[NG * HID];
__device__ float d_gvec[HID];
__device__ float d_newadj[NG * 4];
__device__ float d_scal[4];

// ---------------- ptx helpers ----------------------------------------------
__device__ __forceinline__ uint32_t s2u(const void* p) {
    uint32_t a;
    asm("{ .reg .u64 t; cvta.to.shared.u64 t, %1; cvt.u32.u64 %0, t; }"
        : "=r"(a) : "l"(p));
    return a;
}
__device__ __forceinline__ void cp16(uint32_t s, const void* g) {
    asm volatile("cp.async.cg.shared.global [%0], [%1], 16;" :: "r"(s), "l"(g));
}
__device__ __forceinline__ void mma_f16(float* c, const uint32_t* a, const uint32_t* b) {
    asm volatile(
        "mma.sync.aligned.m16n8k16.row.col.f32.f16.f16.f32 "
        "{%0,%1,%2,%3}, {%4,%5,%6,%7}, {%8,%9}, {%0,%1,%2,%3};"
        : "+f"(c[0]), "+f"(c[1]), "+f"(c[2]), "+f"(c[3])
        : "r"(a[0]), "r"(a[1]), "r"(a[2]), "r"(a[3]), "r"(b[0]), "r"(b[1]));
}
__device__ __forceinline__ void ldm4(uint32_t* r, uint32_t addr) {
    asm volatile("ldmatrix.sync.aligned.m8n8.x4.shared.b16 {%0,%1,%2,%3}, [%4];"
                 : "=r"(r[0]), "=r"(r[1]), "=r"(r[2]), "=r"(r[3]) : "r"(addr));
}
__device__ __forceinline__ void ldm4t(uint32_t* r, uint32_t addr) {
    asm volatile("ldmatrix.sync.aligned.m8n8.x4.trans.shared.b16 {%0,%1,%2,%3}, [%4];"
                 : "=r"(r[0]), "=r"(r[1]), "=r"(r[2]), "=r"(r[3]) : "r"(addr));
}

// ---------------- fused per-graph structure build ---------------------------
__global__ void __launch_bounds__(256) k_build(const int* __restrict__ ei) {
    __shared__ float Adj[NPG * NPG];
    __shared__ float deg[NPG];
    __shared__ float dis[NPG];
    int g = blockIdx.x, tid = threadIdx.x;
    for (int i = tid; i < NPG * NPG; i += 256) Adj[i] = 0.f;
    if (tid < NPG) deg[tid] = 0.f;
    __syncthreads();
    const int* src = ei + g * EPG;
    const int* dst = ei + N_EDGES + g * EPG;
    int base = g * NPG;
    for (int e = tid; e < EPG; e += 256) atomicAdd(&deg[dst[e] - base], 1.f);
    __syncthreads();
    if (tid < NPG) dis[tid] = rsqrtf(deg[tid] + 1.f);
    __syncthreads();
    for (int e = tid; e < EPG; e += 256) {
        int s = src[e] - base, d = dst[e] - base;
        atomicAdd(&Adj[d * NPG + s], dis[s] * dis[d]);
    }
    __syncthreads();
    if (tid < NPG) Adj[tid * NPG + tid] += dis[tid] * dis[tid];
    __syncthreads();
    __half2* out = (__half2*)(d_Ah + (size_t)g * 128 * 120);
    for (int i = tid; i < 128 * 60; i += 256) {
        int r = i / 60, k = (i % 60) * 2;
        float v0 = (r < NPG && k < NPG) ? Adj[r * NPG + k] : 0.f;
        float v1 = (r < NPG && k + 1 < NPG) ? Adj[r * NPG + k + 1] : 0.f;
        out[i] = __floats2half2_rn(v0, v1);
    }
}

__global__ void k_zero_misc() {   // grid 100 x 1024
    int i = blockIdx.x * 1024 + threadIdx.x;
    if (i < N_NODES * 2) d_araw[i] = 0.f;
    if (i < HID) d_gvec[i] = 0.f;
    if (i < 4) d_scal[i] = 0.f;
}

// ---------------- weight transpose to half: Wt[n][k] = h(W[k][n]) -----------
__global__ void k_transpose_h(const float* __restrict__ W, __half* __restrict__ Wt,
                              int K, int N) {
    __shared__ float tile[32][33];
    int k0 = blockIdx.y * 32, n0 = blockIdx.x * 32;
    int tx = threadIdx.x, ty = threadIdx.y;
    for (int j = ty; j < 32; j += 8) tile[j][tx] = W[(size_t)(k0 + j) * N + n0 + tx];
    __syncthreads();
    for (int j = ty; j < 32; j += 8)
        Wt[(size_t)(n0 + j) * K + k0 + tx] = __float2half_rn(tile[tx][j]);
}

__global__ void k_x2h(const float2* __restrict__ x, __half2* __restrict__ o) {
    int i = blockIdx.x * blockDim.x + threadIdx.x;
    if (i < N_NODES * FIN / 2) o[i] = __float22half2_rn(x[i]);
}

// ---------------- fp16 mma GEMM: C[M,512] = A[M,K] @ Wt[512,K]^T ------------
// 256x128 CTA tile, 8 warps as 4x2 (64x64 warp tile), BK=32, 3-stage cp.async,
// single-sync pipeline, ldmatrix fragments.
// EPI: 0 = plain half out, 2 = fused assignment head (tanh + Wc2 dot + atomic)
#define STB_A (256 * 40 * 2)
#define STB_B (128 * 40 * 2)
#define HG_SMEM (3 * (STB_A + STB_B))
template <int K, int EPI>
__global__ void __launch_bounds__(256) hgemm(const __half* __restrict__ A,
                                             const __half* __restrict__ Bt,
                                             const float* __restrict__ bias,
                                             __half* __restrict__ C,
                                             const float* __restrict__ wc2) {
    constexpr int NT = K / 32;
    extern __shared__ __half hsh[];
    __half* As = hsh;                        // 3 x 256*40
    __half* Bs = hsh + 3 * 256 * 40;         // 3 x 128*40
    int tid = threadIdx.x;
    int wid = tid >> 5, lane = tid & 31;
    int g = lane >> 2, q = lane & 3;
    int wm = wid >> 1, wn = wid & 1;
    int m0 = blockIdx.y * 256, n0 = blockIdx.x * 128;

    int lr = tid >> 1, lc = tid & 1;   // row 0..127, half-row chunk
    const __half* Ag0 = A + (size_t)(m0 + lr) * K + lc * 16;
    const __half* Ag1 = A + (size_t)(m0 + lr + 128) * K + lc * 16;
    const __half* Bg = Bt + (size_t)(n0 + lr) * K + lc * 16;
    uint32_t sa0 = s2u(&As[lr * 40 + lc * 16]);
    uint32_t sa1 = s2u(&As[(lr + 128) * 40 + lc * 16]);
    uint32_t sb = s2u(&Bs[lr * 40 + lc * 16]);

    auto load_stage = [&](int kt, int st) {
        uint32_t oA = st * STB_A, oB = st * STB_B;
        cp16(sa0 + oA, Ag0 + kt * 32);
        cp16(sa0 + oA + 16, Ag0 + kt * 32 + 8);
        cp16(sa1 + oA, Ag1 + kt * 32);
        cp16(sa1 + oA + 16, Ag1 + kt * 32 + 8);
        cp16(sb + oB, Bg + kt * 32);
        cp16(sb + oB + 16, Bg + kt * 32 + 8);
        asm volatile("cp.async.commit_group;" ::: "memory");
    };

    uint32_t AsU = s2u(As), BsU = s2u(Bs);
    int laneA = (wm * 64 + (lane & 15)) * 40 + ((lane >> 4) & 1) * 8;
    int laneB = (wn * 64 + ((lane >> 4) & 1) * 8 + (lane & 7)) * 40
                + ((lane >> 3) & 1) * 8;

    float acc[4][8][4];
#pragma unroll
    for (int i = 0; i < 4; ++i)
#pragma unroll
        for (int j = 0; j < 8; ++j)
#pragma unroll
            for (int t = 0; t < 4; ++t) acc[i][j][t] = 0.f;

    load_stage(0, 0);
    if (NT > 1) load_stage(1, 1);

#pragma unroll 1
    for (int kt = 0; kt < NT; ++kt) {
        if (kt + 1 < NT) asm volatile("cp.async.wait_group 1;" ::: "memory");
        else             asm volatile("cp.async.wait_group 0;" ::: "memory");
        __syncthreads();
        if (kt + 2 < NT) load_stage(kt + 2, (kt + 2) % 3);

        uint32_t soA = (kt % 3) * STB_A, soB = (kt % 3) * STB_B;
#pragma unroll
        for (int ks = 0; ks < 2; ++ks) {
            uint32_t ko = ks * 32;   // bytes (16 halves)
            uint32_t af[4][4];
#pragma unroll
            for (int mi = 0; mi < 4; ++mi)
                ldm4(af[mi], AsU + soA + (laneA + mi * 16 * 40) * 2 + ko);
#pragma unroll
            for (int p = 0; p < 4; ++p) {
                uint32_t bf[4];
                ldm4(bf, BsU + soB + (laneB + p * 16 * 40) * 2 + ko);
#pragma unroll
                for (int mi = 0; mi < 4; ++mi) {
                    mma_f16(acc[mi][2 * p], af[mi], bf);
                    mma_f16(acc[mi][2 * p + 1], af[mi], bf + 2);
                }
            }
        }
    }

    if (EPI == 0) {
#pragma unroll
        for (int mi = 0; mi < 4; ++mi) {
            int row0 = m0 + wm * 64 + mi * 16 + g;
#pragma unroll
            for (int ni = 0; ni < 8; ++ni) {
                int col = n0 + wn * 64 + ni * 8 + 2 * q;
                *(half2*)(C + (size_t)row0 * HID + col) =
                    __floats2half2_rn(acc[mi][ni][0], acc[mi][ni][1]);
                *(half2*)(C + (size_t)(row0 + 8) * HID + col) =
                    __floats2half2_rn(acc[mi][ni][2], acc[mi][ni][3]);
            }
        }
    } else {
        // fused assignment head: s = sum_col tanh(acc+bc1[col]) * Wc2[col][:]
        float s[4][2][2];
#pragma unroll
        for (int mi = 0; mi < 4; ++mi)
#pragma unroll
            for (int r = 0; r < 2; ++r) { s[mi][r][0] = 0.f; s[mi][r][1] = 0.f; }
#pragma unroll
        for (int ni = 0; ni < 8; ++ni) {
            int col = n0 + wn * 64 + ni * 8 + 2 * q;
            float4 w4 = *(const float4*)(wc2 + col * 2);
            float2 bb = *(const float2*)(bias + col);
#pragma unroll
            for (int mi = 0; mi < 4; ++mi) {
                float v0 = tanhf(acc[mi][ni][0] + bb.x);
                float v1 = tanhf(acc[mi][ni][1] + bb.y);
                float v2 = tanhf(acc[mi][ni][2] + bb.x);
                float v3 = tanhf(acc[mi][ni][3] + bb.y);
                s[mi][0][0] += v0 * w4.x + v1 * w4.z;
                s[mi][0][1] += v0 * w4.y + v1 * w4.w;
                s[mi][1][0] += v2 * w4.x + v3 * w4.z;
                s[mi][1][1] += v2 * w4.y + v3 * w4.w;
            }
        }
#pragma unroll
        for (int mi = 0; mi < 4; ++mi)
#pragma unroll
            for (int r = 0; r < 2; ++r)
#pragma unroll
                for (int c = 0; c < 2; ++c) {
                    float v = s[mi][r][c];
                    v += __shfl_xor_sync(0xffffffff, v, 1);
                    v += __shfl_xor_sync(0xffffffff, v, 2);
                    s[mi][r][c] = v;
                }
        if (q == 0) {
#pragma unroll
            for (int mi = 0; mi < 4; ++mi)
#pragma unroll
                for (int r = 0; r < 2; ++r) {
                    int row = m0 + wm * 64 + mi * 16 + g + r * 8;
                    atomicAdd(&d_araw[row * 2], s[mi][r][0]);
                    atomicAdd(&d_araw[row * 2 + 1], s[mi][r][1]);
                }
        }
    }
}

// ---------------- tensor-core agg: H = A_g @ T_g + b ------------------------
// Ts stored [k:112][n:128] (row stride 136 halves), B frags via ldmatrix.trans.
#define TS_LD 136
#define AGGH_SMEM ((128 * 120 + 112 * TS_LD) * 2)
__global__ void __launch_bounds__(256) k_aggh(const __half* __restrict__ T,
                                              const float* __restrict__ bias,
                                              __half* __restrict__ Hh) {
    extern __shared__ __half aggsh[];
    __half* Ash = aggsh;                   // [128][120]
    __half* Ts = aggsh + 128 * 120;        // [112][136]
    int gph = blockIdx.x;
    int cb = blockIdx.y * 128;
    int tid = threadIdx.x;
    int wid = tid >> 5, lane = tid & 31;
    int g = lane >> 2, q = lane & 3;
    int wm = wid >> 1, wn = wid & 1;

    const uint4* Asrc = (const uint4*)(d_Ah + (size_t)gph * 128 * 120);
    uint4* Adst = (uint4*)Ash;
    for (int i = tid; i < 128 * 120 / 8; i += 256) Adst[i] = Asrc[i];

    // Ts[k][n] direct copy: 16 x uint4 (=128 halves) per row, zero pad k 100..111
    const __half* Tg = T + (size_t)gph * NPG * HID + cb;
    const uint4 z4 = make_uint4(0, 0, 0, 0);
    for (int i = tid; i < 112 * 16; i += 256) {
        int k = i >> 4, c = i & 15;
        uint4 v = (k < NPG) ? *(const uint4*)(Tg + (size_t)k * HID + c * 8) : z4;
        *(uint4*)(Ts + k * TS_LD + c * 8) = v;
    }
    __syncthreads();

    uint32_t AshU = s2u(Ash), TsU = s2u(Ts);
    int laneA = (wm * 32 + (lane & 15)) * 120 + ((lane >> 4) & 1) * 8;
    int laneBt = (lane & 15) * TS_LD + wn * 64 + ((lane >> 4) & 1) * 8;

    float acc[2][8][4];
#pragma unroll
    for (int i = 0; i < 2; ++i)
#pragma unroll
        for (int j = 0; j < 8; ++j)
#pragma unroll
            for (int t = 0; t < 4; ++t) acc[i][j][t] = 0.f;

#pragma unroll
    for (int k0 = 0; k0 < 112; k0 += 16) {
        uint32_t af[2][4];
#pragma unroll
        for (int mi = 0; mi < 2; ++mi)
            ldm4(af[mi], AshU + (laneA + mi * 16 * 120 + k0) * 2);
#pragma unroll
        for (int p = 0; p < 4; ++p) {
            uint32_t bf[4];
            ldm4t(bf, TsU + (laneBt + k0 * TS_LD + p * 16) * 2);
#pragma unroll
            for (int mi = 0; mi < 2; ++mi) {
                mma_f16(acc[mi][2 * p], af[mi], bf);
                mma_f16(acc[mi][2 * p + 1], af[mi], bf + 2);
            }
        }
    }

#pragma unroll
    for (int mi = 0; mi < 2; ++mi) {
        int rl = wm * 32 + mi * 16 + g;
#pragma unroll
        for (int ni = 0; ni < 8; ++ni) {
            int col = cb + wn * 64 + ni * 8 + 2 * q;
            float2 bb = *(const float2*)(bias + col);
            if (rl < NPG) {
                size_t off = ((size_t)gph * NPG + rl) * HID + col;
                *(half2*)(Hh + off) =
                    __floats2half2_rn(acc[mi][ni][0] + bb.x, acc[mi][ni][1] + bb.y);
            }
            if (rl + 8 < NPG) {
                size_t off = ((size_t)gph * NPG + rl + 8) * HID + col;
                *(half2*)(Hh + off) =
                    __floats2half2_rn(acc[mi][ni][2] + bb.x, acc[mi][ni][3] + bb.y);
            }
        }
    }
}

// ---------------- fp32 tiled SGEMM (head only) ------------------------------
template <int EPI>
__global__ void sgemm(const float* __restrict__ A, const float* __restrict__ B,
                      const float* __restrict__ bias, float* __restrict__ C,
                      int M, int N, int K) {
    __shared__ float As[8][128];
    __shared__ float Bs[8][128];
    int tid = threadIdx.x;
    int m0 = blockIdx.y * 128;
    int n0 = blockIdx.x * 128;
    int arow = tid >> 1;
    int acol = (tid & 1) * 4;
    int brow = tid >> 5;
    int bcol = (tid & 31) * 4;
    int ty = tid >> 4;
    int tx = tid & 15;
    float acc[8][8] = {};

    for (int k0 = 0; k0 < K; k0 += 8) {
        float4 av = *(const float4*)(A + (size_t)(m0 + arow) * K + k0 + acol);
        As[acol + 0][arow] = av.x;
        As[acol + 1][arow] = av.y;
        As[acol + 2][arow] = av.z;
        As[acol + 3][arow] = av.w;
        *(float4*)(&Bs[brow][bcol]) =
            *(const float4*)(B + (size_t)(k0 + brow) * N + n0 + bcol);
        __syncthreads();
#pragma unroll
        for (int k = 0; k < 8; ++k) {
            float a[8], b[8];
            *(float4*)(a) = *(float4*)(&As[k][ty * 8]);
            *(float4*)(a + 4) = *(float4*)(&As[k][ty * 8 + 4]);
            *(float4*)(b) = *(float4*)(&Bs[k][tx * 8]);
            *(float4*)(b + 4) = *(float4*)(&Bs[k][tx * 8 + 4]);
#pragma unroll
            for (int i = 0; i < 8; ++i)
#pragma unroll
                for (int j = 0; j < 8; ++j) acc[i][j] = fmaf(a[i], b[j], acc[i][j]);
        }
        __syncthreads();
    }
#pragma unroll
    for (int i = 0; i < 8; ++i) {
        int row = m0 + ty * 8 + i;
#pragma unroll
        for (int j = 0; j < 8; j += 4) {
            int col = n0 + tx * 8 + j;
            float4 v = make_float4(acc[i][j], acc[i][j + 1], acc[i][j + 2], acc[i][j + 3]);
            if (EPI != 0) {
                float4 bb = *(const float4*)(bias + col);
                v.x += bb.x; v.y += bb.y; v.z += bb.z; v.w += bb.w;
                if (EPI == 1) {
                    v.x = tanhf(v.x); v.y = tanhf(v.y); v.z = tanhf(v.z); v.w = tanhf(v.w);
                } else {
                    v.x = fmaxf(v.x, 0.f); v.y = fmaxf(v.y, 0.f);
                    v.z = fmaxf(v.z, 0.f); v.w = fmaxf(v.w, 0.f);
                }
            }
            *(float4*)(C + (size_t)row * N + col) = v;
        }
    }
}

// ---------------- assignment softmax from raw logits ------------------------
__global__ void k_assign2(const float* __restrict__ bc2) {
    int n = blockIdx.x * blockDim.x + threadIdx.x;
    if (n < N_NODES) {
        float z0 = d_araw[2 * n] + bc2[0], z1 = d_araw[2 * n + 1] + bc2[1];
        float m = fmaxf(z0, z1);
        float e0 = expf(z0 - m), e1 = expf(z1 - m);
        float inv = 1.f / (e0 + e1);
        d_assign[2 * n] = e0 * inv;
        d_assign[2 * n + 1] = e1 * inv;
    }
}

// ---------------- pos + global h column sums (reads half h) -----------------
__global__ void k_pos(const __half* __restrict__ H) {
    __shared__ float a0[NPG];
    int g = blockIdx.x, c = threadIdx.x;
    if (c < NPG) a0[c] = d_assign[(g * NPG + c) * 2];
    __syncthreads();
    const __half* h = H + (size_t)g * NPG * HID;
    float acc = 0.f, gs = 0.f;
    for (int n = 0; n < NPG; ++n) {
        float hv = __half2float(h[n * HID + c]);
        acc = fmaf(a0[n], hv, acc);
        gs += hv;
    }
    d_pos[g * HID + c] = acc;
    atomicAdd(&d_gvec[c], gs);
}

// ---------------- new_adj + penalty ----------------------------------------
__global__ void k_newadj(const int* __restrict__ ei) {
    __shared__ float sa[NPG * 2];
    __shared__ float red[4][4];
    int g = blockIdx.x, tid = threadIdx.x;
    if (tid < NPG * 2) sa[tid] = d_assign[g * NPG * 2 + tid];
    __syncthreads();
    float a00 = 0, a01 = 0, a10 = 0, a11 = 0;
    for (int e = tid; e < EPG; e += 128) {
        int s = ei[g * EPG + e] - g * NPG;
        int d = ei[N_EDGES + g * EPG + e] - g * NPG;
        float s0 = sa[2 * s], s1 = sa[2 * s + 1];
        float t0 = sa[2 * d], t1 = sa[2 * d + 1];
        a00 = fmaf(s0, t0, a00); a01 = fmaf(s0, t1, a01);
        a10 = fmaf(s1, t0, a10); a11 = fmaf(s1, t1, a11);
    }
#pragma unroll
    for (int o = 16; o > 0; o >>= 1) {
        a00 += __shfl_xor_sync(0xffffffff, a00, o);
        a01 += __shfl_xor_sync(0xffffffff, a01, o);
        a10 += __shfl_xor_sync(0xffffffff, a10, o);
        a11 += __shfl_xor_sync(0xffffffff, a11, o);
    }
    int warp = tid >> 5, lane = tid & 31;
    if (lane == 0) {
        red[warp][0] = a00; red[warp][1] = a01;
        red[warp][2] = a10; red[warp][3] = a11;
    }
    __syncthreads();
    if (tid < 4) {
        float v = red[0][tid] + red[1][tid] + red[2][tid] + red[3][tid];
        d_newadj[g * 4 + tid] = v;
    }
}

__global__ void k_penalty(float* __restrict__ out) {
    __shared__ float red[NG];
    int g = threadIdx.x;
    float a00 = d_newadj[g * 4], a01 = d_newadj[g * 4 + 1];
    float a10 = d_newadj[g * 4 + 2], a11 = d_newadj[g * 4 + 3];
    float r0 = fmaxf(fabsf(a00) + fabsf(a01), EPSV);
    float r1 = fmaxf(fabsf(a10) + fabsf(a11), EPSV);
    float dd0 = a00 / r0 - 1.f, dd1 = a11 / r1 - 1.f;
    red[g] = dd0 * dd0 + dd1 * dd1;
    __syncthreads();
    for (int s = 256; s > 0; s >>= 1) {
        if (g < s) red[g] += red[g + s];
        __syncthreads();
    }
    if (g == 0) out[OUT_PEN] = red[0] * (1.f / (NG * 2.f));
}

// ---------------- norm reductions ------------------------------------------
__global__ void k_sumsq_pos() {
    __shared__ float red[256];
    int tid = threadIdx.x;
    float s = 0.f;
    for (int i = blockIdx.x * 256 + tid; i < NG * HID; i += gridDim.x * 256) {
        float v = d_pos[i];
        s = fmaf(v, v, s);
    }
    red[tid] = s;
    __syncthreads();
    for (int o = 128; o > 0; o >>= 1) {
        if (tid < o) red[tid] += red[tid + o];
        __syncthreads();
    }
    if (tid == 0) atomicAdd(&d_scal[0], red[0]);
}

__global__ void k_pg() {
    __shared__ float red[HID];
    int t = threadIdx.x;
    float v = d_gvec[t] * (1.f / (float)N_NODES);
    red[t] = v * v;
    __syncthreads();
    for (int s = 256; s > 0; s >>= 1) {
        if (t < s) red[t] += red[t + s];
        __syncthreads();
    }
    if (t == 0) d_scal[1] = red[0] * (1.f / (float)HID);
}

__global__ void k_finpos(float* __restrict__ out) {
    int i = blockIdx.x * blockDim.x + threadIdx.x;
    if (i < NG * HID) {
        float ms = d_scal[0] * (1.f / (float)(NG * HID));
        float sc = (ms > 1.f) ? rsqrtf(ms) : 1.f;
        float v = d_pos[i] * sc;
        d_pos[i] = v;
        out[OUT_POS + i] = v;
    }
}

__global__ void k_fingemb(float* __restrict__ out) {
    int i = blockIdx.x * blockDim.x + threadIdx.x;
    if (i < NG * HID) {
        float ms = d_scal[1];
        float sc = (ms > 1.f) ? rsqrtf(ms) : 1.f;
        float v = d_gvec[i & (HID - 1)] * (1.f / (float)N_NODES) * sc;
        out[OUT_GEMB + i] = v;
    }
}

// ---------------- head ------------------------------------------------------
__global__ void k_head(const float* __restrict__ Z, const float* __restrict__ Wl2,
                       const float* __restrict__ bl2, float* __restrict__ out) {
    __shared__ float w[HID * 6];
    int tid = threadIdx.x;
    for (int i = tid; i < HID * 6; i += 128) w[i] = Wl2[i];
    __syncthreads();
    int warp = tid >> 5, lane = tid & 31;
    int row = blockIdx.x * 4 + warp;
    const float* z = Z + (size_t)row * HID;
    float s[6] = {0, 0, 0, 0, 0, 0};
    for (int k = lane; k < HID; k += 32) {
        float zv = z[k];
#pragma unroll
        for (int j = 0; j < 6; ++j) s[j] = fmaf(zv, w[k * 6 + j], s[j]);
    }
#pragma unroll
    for (int o = 16; o > 0; o >>= 1)
#pragma unroll
        for (int j = 0; j < 6; ++j) s[j] += __shfl_xor_sync(0xffffffff, s[j], o);
    if (lane == 0) {
        float o6[6], m = -1e30f;
#pragma unroll
        for (int j = 0; j < 6; ++j) { o6[j] = s[j] + bl2[j]; m = fmaxf(m, o6[j]); }
        float sum = 0.f;
#pragma unroll
        for (int j = 0; j < 6; ++j) sum += expf(o6[j] - m);
        float lse = m + logf(sum);
#pragma unroll
        for (int j = 0; j < 6; ++j) out[OUT_LOGP + row * 6 + j] = o6[j] - lse;
    }
}

// ---------------- launch ----------------------------------------------------
extern "C" void kernel_launch(void* const* d_in, const int* in_sizes, int n_in,
                              void* d_out, int out_size) {
    const float* x   = (const float*)d_in[0];
    const int*   ei  = (const int*)d_in[1];
    const float* W1  = (const float*)d_in[4];
    const float* b1  = (const float*)d_in[5];
    const float* W2  = (const float*)d_in[6];
    const float* b2  = (const float*)d_in[7];
    const float* W3  = (const float*)d_in[8];
    const float* b3  = (const float*)d_in[9];
    const float* Wc1 = (const float*)d_in[10];
    const float* bc1 = (const float*)d_in[11];
    const float* Wc2 = (const float*)d_in[12];
    const float* bc2 = (const float*)d_in[13];
    const float* Wl1 = (const float*)d_in[14];
    const float* bl1 = (const float*)d_in[15];
    const float* Wl2 = (const float*)d_in[16];
    const float* bl2 = (const float*)d_in[17];
    float* out = (float*)d_out;

    float *pT, *pPos;
    __half *pTh, *pHh, *pXh, *pWh;
    cudaGetSymbolAddress((void**)&pT, d_T);
    cudaGetSymbolAddress((void**)&pPos, d_pos);
    cudaGetSymbolAddress((void**)&pTh, d_Th);
    cudaGetSymbolAddress((void**)&pHh, d_Hh);
    cudaGetSymbolAddress((void**)&pXh, d_Xh);
    cudaGetSymbolAddress((void**)&pWh, d_Wh);

    cudaFuncSetAttribute(k_aggh, cudaFuncAttributeMaxDynamicSharedMemorySize, AGGH_SMEM);
    cudaFuncSetAttribute(hgemm<FIN, 0>, cudaFuncAttributeMaxDynamicSharedMemorySize, HG_SMEM);
    cudaFuncSetAttribute(hgemm<HID, 0>, cudaFuncAttributeMaxDynamicSharedMemorySize, HG_SMEM);
    cudaFuncSetAttribute(hgemm<HID, 2>, cudaFuncAttributeMaxDynamicSharedMemorySize, HG_SMEM);

    __half* Wh0 = pWh;
    __half* Wh1 = pWh + HID * HID;
    __half* Wh2 = pWh + 2 * HID * HID;
    __half* Wh3 = pWh + 3 * HID * HID;

    // fused graph structure build + misc zero
    k_zero_misc<<<100, 1024>>>();
    k_build<<<NG, 256>>>(ei);

    // weight transposes (fp32 -> half, transposed)
    dim3 tb(32, 8);
    k_transpose_h<<<dim3(HID / 32, FIN / 32), tb>>>(W1, Wh0, FIN, HID);
    k_transpose_h<<<dim3(HID / 32, HID / 32), tb>>>(W2, Wh1, HID, HID);
    k_transpose_h<<<dim3(HID / 32, HID / 32), tb>>>(W3, Wh2, HID, HID);
    k_transpose_h<<<dim3(HID / 32, HID / 32), tb>>>(Wc1, Wh3, HID, HID);
    k_x2h<<<(N_NODES * FIN / 2 + 255) / 256, 256>>>((const float2*)x, (__half2*)pXh);

    dim3 gBig(HID / 128, N_NODES / 256);
    dim3 gAgg(NG, 4);

    // 3 GCN layers: T = H@W (fp16 tensor) ; H = A_hat @ T + b (fp16 tensor)
    hgemm<FIN, 0><<<gBig, 256, HG_SMEM>>>(pXh, Wh0, nullptr, pTh, nullptr);
    k_aggh<<<gAgg, 256, AGGH_SMEM>>>(pTh, b1, pHh);
    hgemm<HID, 0><<<gBig, 256, HG_SMEM>>>(pHh, Wh1, nullptr, pTh, nullptr);
    k_aggh<<<gAgg, 256, AGGH_SMEM>>>(pTh, b2, pHh);
    hgemm<HID, 0><<<gBig, 256, HG_SMEM>>>(pHh, Wh2, nullptr, pTh, nullptr);
    k_aggh<<<gAgg, 256, AGGH_SMEM>>>(pTh, b3, pHh);

    // assignment fused into 4th GEMM epilogue, then softmax
    hgemm<HID, 2><<<gBig, 256, HG_SMEM>>>(pHh, Wh3, bc1, pTh, Wc2);
    k_assign2<<<(N_NODES + 255) / 256, 256>>>(bc2);

    // pooling / penalty
    k_pos<<<NG, HID>>>(pHh);
    k_newadj<<<NG, 128>>>(ei);
    k_penalty<<<1, NG>>>(out);

    // normalizations
    k_sumsq_pos<<<256, 256>>>();
    k_pg<<<1, HID>>>();
    k_finpos<<<1024, 256>>>(out);
    k_fingemb<<<1024, 256>>>(out);

    // head MLP on normalized pos (fp32)
    dim3 gHead(HID / 128, NG / 128);
    sgemm<2><<<gHead, 256>>>(pPos, Wl1, bl1, pT, NG, HID, HID);
    k_head<<<NG / 4, 128>>>(pT, Wl2, bl2, out);
}